// round 7
// baseline (speedup 1.0000x reference)
#include <cuda_runtime.h>
#include <cstdint>

// ---------------------------------------------------------------------------
// Transformer block, bf16x3 split-precision mma.sync GEMMs.
// R7: 512-thread GEMM CTAs (tile 128x256, warp 64x32) -> 4 warps/SMSP for
// latency hiding (R6 capture showed occ=12.3%, tensor=40%).
// B=384, S=128, E=512, H=4, D=128, F=2048.
// ---------------------------------------------------------------------------

constexpr int Bb = 384, Ss = 128, Ee = 512, Hh = 4, Ff = 2048;
constexpr int MM   = Bb * Ss;          // 49152
constexpr int NQKV = 3 * Ee;           // 1536

// -------------------- scratch (static device arrays) -----------------------
__device__ uint16_t g_xh [(size_t)MM * Ee], g_xl [(size_t)MM * Ee];
__device__ uint16_t g_qh [(size_t)MM * NQKV], g_ql [(size_t)MM * NQKV];
__device__ uint16_t g_ath[(size_t)MM * Ee], g_atl[(size_t)MM * Ee];
__device__ float    g_x1f[(size_t)MM * Ee];
__device__ uint16_t g_x1h[(size_t)MM * Ee], g_x1l[(size_t)MM * Ee];
__device__ uint16_t g_hh [(size_t)MM * Ff], g_hl [(size_t)MM * Ff];
__device__ uint16_t g_wqkvh[(size_t)NQKV * Ee], g_wqkvl[(size_t)NQKV * Ee];
__device__ uint16_t g_woh[(size_t)Ee * Ee],  g_wol[(size_t)Ee * Ee];
__device__ uint16_t g_w1h[(size_t)Ff * Ee],  g_w1l[(size_t)Ff * Ee];
__device__ uint16_t g_w2h[(size_t)Ee * Ff],  g_w2l[(size_t)Ee * Ff];
__device__ float    g_bqkv[NQKV];

// -------------------- helpers ----------------------------------------------
__device__ __forceinline__ void split2(float v, uint16_t& h, uint16_t& l) {
    float hf;
    asm("cvt.rn.bf16.f32 %0, %1;" : "=h"(h) : "f"(v));
    asm("cvt.f32.bf16 %0, %1;"    : "=f"(hf) : "h"(h));
    asm("cvt.rn.bf16.f32 %0, %1;" : "=h"(l) : "f"(v - hf));
}
__device__ __forceinline__ uint32_t cvta_s(const void* p) {
    uint32_t a;
    asm("{\n\t.reg .u64 t;\n\tcvta.to.shared.u64 t, %1;\n\tcvt.u32.u64 %0, t;\n\t}"
        : "=r"(a) : "l"(p));
    return a;
}

#define CP16(s, g)  asm volatile("cp.async.cg.shared.global [%0], [%1], 16;" ::"r"(s), "l"(g))
#define CPCOMMIT()  asm volatile("cp.async.commit_group;" ::: "memory")

__device__ __forceinline__ void cpwait(int n) {
    if (n >= 2)      asm volatile("cp.async.wait_group 2;" ::: "memory");
    else if (n == 1) asm volatile("cp.async.wait_group 1;" ::: "memory");
    else             asm volatile("cp.async.wait_group 0;" ::: "memory");
}

#define LDSM4(r0, r1, r2, r3, a) \
    asm volatile("ldmatrix.sync.aligned.m8n8.x4.shared.b16 {%0,%1,%2,%3}, [%4];" \
        : "=r"(r0), "=r"(r1), "=r"(r2), "=r"(r3) : "r"(a))
#define LDSM4T(r0, r1, r2, r3, a) \
    asm volatile("ldmatrix.sync.aligned.m8n8.x4.trans.shared.b16 {%0,%1,%2,%3}, [%4];" \
        : "=r"(r0), "=r"(r1), "=r"(r2), "=r"(r3) : "r"(a))
#define STS32(a, v) asm volatile("st.shared.b32 [%0], %1;" ::"r"(a), "r"(v) : "memory")

__device__ __forceinline__ void mma16(float* d, const uint32_t* a,
                                      uint32_t b0, uint32_t b1) {
    asm volatile(
        "mma.sync.aligned.m16n8k16.row.col.f32.bf16.bf16.f32 "
        "{%0,%1,%2,%3}, {%4,%5,%6,%7}, {%8,%9}, {%0,%1,%2,%3};\n"
        : "+f"(d[0]), "+f"(d[1]), "+f"(d[2]), "+f"(d[3])
        : "r"(a[0]), "r"(a[1]), "r"(a[2]), "r"(a[3]), "r"(b0), "r"(b1));
}
__device__ __forceinline__ void mma3(float* d, const uint32_t* ah, const uint32_t* al,
                                     uint32_t bh0, uint32_t bh1,
                                     uint32_t bl0, uint32_t bl1) {
    mma16(d, ah, bh0, bh1);
    mma16(d, al, bh0, bh1);
    mma16(d, ah, bl0, bl1);
}

// ---------------------------------------------------------------------------
// merged prep: split x + concat bias + transpose/split all weights
// ---------------------------------------------------------------------------
__global__ void prep_all(const float* __restrict__ x,
                         const float* __restrict__ bq, const float* __restrict__ bk,
                         const float* __restrict__ bv,
                         const float* __restrict__ wq, const float* __restrict__ wk,
                         const float* __restrict__ wv, const float* __restrict__ wo,
                         const float* __restrict__ w1, const float* __restrict__ w2) {
    __shared__ uint32_t tile[32][33];
    const int bidx = blockIdx.x;
    if (bidx < 12288) {
        const size_t base = ((size_t)bidx * 256 + threadIdx.x) * 8;
        const float4 v0 = *(const float4*)(x + base);
        const float4 v1 = *(const float4*)(x + base + 4);
        uint16_t h[8], l[8];
        split2(v0.x, h[0], l[0]); split2(v0.y, h[1], l[1]);
        split2(v0.z, h[2], l[2]); split2(v0.w, h[3], l[3]);
        split2(v1.x, h[4], l[4]); split2(v1.y, h[5], l[5]);
        split2(v1.z, h[6], l[6]); split2(v1.w, h[7], l[7]);
        uint4 oh, ol;
        oh.x = h[0] | (h[1] << 16); oh.y = h[2] | (h[3] << 16);
        oh.z = h[4] | (h[5] << 16); oh.w = h[6] | (h[7] << 16);
        ol.x = l[0] | (l[1] << 16); ol.y = l[2] | (l[3] << 16);
        ol.z = l[4] | (l[5] << 16); ol.w = l[6] | (l[7] << 16);
        *(uint4*)(g_xh + base) = oh;
        *(uint4*)(g_xl + base) = ol;
        return;
    }
    if (bidx < 12294) {
        const int i = (bidx - 12288) * 256 + threadIdx.x;
        if (i < NQKV)
            g_bqkv[i] = i < 512 ? bq[i] : (i < 1024 ? bk[i - 512] : bv[i - 1024]);
        return;
    }
    const int id = bidx - 12294;
    const float* W; uint16_t *Dh, *Dl;
    int Nsrc, Kd, tx, ty, rowoff = 0;
    if (id < 768) {
        const int w = id >> 8, loc = id & 255;
        tx = loc & 15; ty = loc >> 4;
        W = w == 0 ? wq : (w == 1 ? wk : wv);
        Dh = g_wqkvh; Dl = g_wqkvl; Nsrc = 512; Kd = 512; rowoff = w * 512;
    } else if (id < 1024) {
        const int loc = id - 768; tx = loc & 15; ty = loc >> 4;
        W = wo; Dh = g_woh; Dl = g_wol; Nsrc = 512; Kd = 512;
    } else if (id < 2048) {
        const int loc = id - 1024; tx = loc & 63; ty = loc >> 6;
        W = w1; Dh = g_w1h; Dl = g_w1l; Nsrc = 2048; Kd = 512;
    } else {
        const int loc = id - 2048; tx = loc & 15; ty = loc >> 4;
        W = w2; Dh = g_w2h; Dl = g_w2l; Nsrc = 512; Kd = 2048;
    }
    const int kb = ty * 32, nb = tx * 32;
    const int lx = threadIdx.x & 31, ly = threadIdx.x >> 5;
    for (int j = ly; j < 32; j += 8) {
        uint16_t h, l;
        split2(W[(size_t)(kb + j) * Nsrc + nb + lx], h, l);
        tile[j][lx] = (uint32_t)h | ((uint32_t)l << 16);
    }
    __syncthreads();
    for (int j = ly; j < 32; j += 8) {
        const uint32_t u = tile[lx][j];
        const size_t o = (size_t)(rowoff + nb + j) * Kd + kb + lx;
        Dh[o] = (uint16_t)u;
        Dl[o] = (uint16_t)(u >> 16);
    }
}

// ---------------------------------------------------------------------------
// GEMM: C = epi(A[M,K] @ B[N,K]^T + bias [, res]), bf16x3 via ldmatrix+HMMA.
// CTA: 512 threads, tile 128(M)x256(N), BK=32, 4-stage cp.async,
// warp grid 2(M)x8(N), warp tile 64x32 (acc=64 regs) -> 4 warps/SMSP.
// smem row = 128B: chunks 0-3 hi(k0..31), 4-7 lo; phys chunk = c ^ (row&7).
// EPI: 0 = planes; 1 = +res, f32+planes; 2 = relu, planes; 3 = +res, f32.
// ---------------------------------------------------------------------------
constexpr int ST   = 4;
constexpr int A_BYTES = 128 * 128;             // 16384
constexpr int B_OFF   = A_BYTES;
constexpr int STGB    = A_BYTES + 256 * 128;   // 49152
constexpr int SMEM_G  = ST * STGB;             // 196608

template <int EPI>
__device__ __forceinline__ void epi2(float* __restrict__ Cf,
                                     uint16_t* __restrict__ Ch, uint16_t* __restrict__ Cl,
                                     const float* __restrict__ bias,
                                     const float* __restrict__ res,
                                     int r, int c, int N, float v0, float v1) {
    v0 += bias[c]; v1 += bias[c + 1];
    if (EPI == 1 || EPI == 3) {
        const float2 rv = *(const float2*)(res + (size_t)r * N + c);
        v0 += rv.x; v1 += rv.y;
    }
    if (EPI == 2) { v0 = fmaxf(v0, 0.f); v1 = fmaxf(v1, 0.f); }
    if (EPI == 1 || EPI == 3)
        *(float2*)(Cf + (size_t)r * N + c) = make_float2(v0, v1);
    if (EPI != 3) {
        uint16_t h0, l0, h1, l1;
        split2(v0, h0, l0); split2(v1, h1, l1);
        *(uint32_t*)(Ch + (size_t)r * N + c) = (uint32_t)h0 | ((uint32_t)h1 << 16);
        *(uint32_t*)(Cl + (size_t)r * N + c) = (uint32_t)l0 | ((uint32_t)l1 << 16);
    }
}

template <int EPI>
__global__ __launch_bounds__(512, 1)
void gemm_p(const uint16_t* __restrict__ Ah_, const uint16_t* __restrict__ Al_,
            const uint16_t* __restrict__ Bh_, const uint16_t* __restrict__ Bl_,
            const float* __restrict__ bias, const float* __restrict__ res,
            float* __restrict__ Cf,
            uint16_t* __restrict__ Ch, uint16_t* __restrict__ Cl,
            int Nout, int K) {
    extern __shared__ char smraw[];
    const uint32_t sb = cvta_s(smraw);

    const int tid = threadIdx.x, wid = tid >> 5, lane = tid & 31;
    const int wm = wid >> 3, wn = wid & 7;         // 2(M) x 8(N) warp grid
    const int mB = blockIdx.y * 128, nB = blockIdx.x * 256;
    const int l7 = lane & 7, l8 = (lane >> 3) & 1, l16 = lane >> 4;

    // ---- load geometry: 3072 16B-chunks/stage, 6 per thread ----
    // rows: A 0..127 (i=0,1), B 0..255 (i=2..5); row0 = tid>>3, step 64 rows/i
    const int row0 = tid >> 3, tch = tid & 7;
    const int kofs = (tch & 3) * 8;
    const uint32_t dst0 = row0 * 128 + (((uint32_t)tch ^ (row0 & 7)) << 4);
    const uint16_t* gA = (tch < 4 ? Ah_ : Al_) + (size_t)(mB + row0) * K + kofs;
    const uint16_t* gB = (tch < 4 ? Bh_ : Bl_) + (size_t)(nB + row0) * K + kofs;
    const size_t rStep = (size_t)64 * K;           // 64 rows per i

    float acc[4][4][4];
#pragma unroll
    for (int a = 0; a < 4; a++)
#pragma unroll
        for (int b = 0; b < 4; b++)
#pragma unroll
            for (int c = 0; c < 4; c++) acc[a][b][c] = 0.f;

    auto issue = [&](int s) {
        const uint32_t stb = sb + (s & (ST - 1)) * STGB;
        const uint16_t* ga = gA + (size_t)s * 32;
        const uint16_t* gb = gB + (size_t)s * 32;
#pragma unroll
        for (int i = 0; i < 2; i++)
            CP16(stb + dst0 + i * 8192, ga + (size_t)i * rStep);
#pragma unroll
        for (int i = 0; i < 4; i++)
            CP16(stb + B_OFF + dst0 + i * 8192, gb + (size_t)i * rStep);
        CPCOMMIT();
    };

    const int nT = K >> 5;
    for (int s = 0; s < ST - 1 && s < nT; s++) issue(s);

    const uint32_t raBase[4] = {
        (uint32_t)(wm * 64 + 0 * 16 + l8 * 8 + l7),
        (uint32_t)(wm * 64 + 1 * 16 + l8 * 8 + l7),
        (uint32_t)(wm * 64 + 2 * 16 + l8 * 8 + l7),
        (uint32_t)(wm * 64 + 3 * 16 + l8 * 8 + l7)};
    const uint32_t rbBase[2] = {
        (uint32_t)(wn * 32 + 0 * 16 + l8 * 8 + l7),
        (uint32_t)(wn * 32 + 1 * 16 + l8 * 8 + l7)};

    for (int t = 0; t < nT; t++) {
        const int rem = nT - 1 - t;
        cpwait(rem < 2 ? rem : 2);
        __syncthreads();
        if (t + ST - 1 < nT) issue(t + ST - 1);

        const uint32_t stb = sb + (t & (ST - 1)) * STGB;
#pragma unroll
        for (int h = 0; h < 2; h++) {
            uint32_t ah[4][4], al[4][4];
#pragma unroll
            for (int mi = 0; mi < 4; mi++) {
                const uint32_t r = raBase[mi];
                const uint32_t base = stb + r * 128;
                const uint32_t ch = (uint32_t)(2 * h + l16) ^ (r & 7);
                const uint32_t cl = (uint32_t)(4 + 2 * h + l16) ^ (r & 7);
                LDSM4(ah[mi][0], ah[mi][1], ah[mi][2], ah[mi][3], base + (ch << 4));
                LDSM4(al[mi][0], al[mi][1], al[mi][2], al[mi][3], base + (cl << 4));
            }
#pragma unroll
            for (int j2 = 0; j2 < 2; j2++) {
                const uint32_t r = rbBase[j2];
                const uint32_t base = stb + B_OFF + r * 128;
                const uint32_t ch = (uint32_t)(2 * h + l16) ^ (r & 7);
                const uint32_t cl = (uint32_t)(4 + 2 * h + l16) ^ (r & 7);
                uint32_t bhm[4], blm[4];
                LDSM4(bhm[0], bhm[1], bhm[2], bhm[3], base + (ch << 4));
                LDSM4(blm[0], blm[1], blm[2], blm[3], base + (cl << 4));
#pragma unroll
                for (int mi = 0; mi < 4; mi++) {
#pragma unroll
                    for (int jj = 0; jj < 2; jj++)
                        mma3(acc[mi][2 * j2 + jj], ah[mi], al[mi],
                             bhm[jj], bhm[2 + jj], blm[jj], blm[2 + jj]);
                }
            }
        }
    }

    // epilogue: warp tile 64x32 at (mB + wm*64, nB + wn*32)
#pragma unroll
    for (int mi = 0; mi < 4; mi++) {
        const int r0 = mB + wm * 64 + mi * 16 + (lane >> 2);
#pragma unroll
        for (int nj = 0; nj < 4; nj++) {
            const int c = nB + wn * 32 + nj * 8 + 2 * (lane & 3);
            epi2<EPI>(Cf, Ch, Cl, bias, res, r0,     c, Nout,
                      acc[mi][nj][0], acc[mi][nj][1]);
            epi2<EPI>(Cf, Ch, Cl, bias, res, r0 + 8, c, Nout,
                      acc[mi][nj][2], acc[mi][nj][3]);
        }
    }
}

// ---------------------------------------------------------------------------
// Attention on bf16 planes (unchanged from R6).
// ---------------------------------------------------------------------------
constexpr int SMEM_ATTN = 6 * 32768;     // 196608

__global__ __launch_bounds__(256, 1)
void attn_kernel(const uint16_t* __restrict__ qh, const uint16_t* __restrict__ ql,
                 uint16_t* __restrict__ Oh, uint16_t* __restrict__ Ol) {
    extern __shared__ char smraw[];
    const uint32_t sb = cvta_s(smraw);
    const uint32_t QH = sb, QL = sb + 32768, KH = sb + 65536, KL = sb + 98304;
    const uint32_t VH = sb + 131072, VL = sb + 163840;

    const int tid = threadIdx.x;
    const int bh  = blockIdx.x;
    const int bb = bh >> 2, head = bh & 3;
    const size_t rowbase = (size_t)bb * Ss * NQKV;
    const int coloff = head * 128;
    const size_t obase = (size_t)bb * Ss * Ee + (size_t)coloff;

#pragma unroll
    for (int i = 0; i < 48; i++) {
        const int idx = tid + i * 256;
        const int p = idx >> 11;
        const int rem = idx & 2047;
        const int row = rem >> 4, c = rem & 15;
        const uint16_t* base = (p & 1) ? ql : qh;
        const size_t src = rowbase + (size_t)row * NQKV + (p >> 1) * 512 + coloff + c * 8;
        const uint32_t dst = sb + p * 32768 + row * 256 + ((uint32_t)(c ^ (row & 7)) << 4);
        CP16(dst, base + src);
    }
    CPCOMMIT();
    cpwait(0);
    __syncthreads();

    const int wid = tid >> 5, lane = tid & 31;
    const int g = lane >> 2, q = lane & 3;
    const int l7 = lane & 7, l8 = (lane >> 3) & 1, l16 = lane >> 4;
    const int rbase = wid * 16;
    const int ra = rbase + l8 * 8 + l7;

    float acc[16][4];
#pragma unroll
    for (int j = 0; j < 16; j++)
#pragma unroll
        for (int c = 0; c < 4; c++) acc[j][c] = 0.f;

#pragma unroll
    for (int kk = 0; kk < 8; kk++) {
        const uint32_t ca = ((uint32_t)((2 * kk + l16) ^ (ra & 7)) << 4) + ra * 256;
        uint32_t ah[4], al[4];
        LDSM4(ah[0], ah[1], ah[2], ah[3], QH + ca);
        LDSM4(al[0], al[1], al[2], al[3], QL + ca);
#pragma unroll
        for (int j2 = 0; j2 < 8; j2++) {
            const int rb = j2 * 16 + l8 * 8 + l7;
            const uint32_t cb = ((uint32_t)((2 * kk + l16) ^ (rb & 7)) << 4) + rb * 256;
            uint32_t bh_[4], bl_[4];
            LDSM4(bh_[0], bh_[1], bh_[2], bh_[3], KH + cb);
            LDSM4(bl_[0], bl_[1], bl_[2], bl_[3], KL + cb);
            mma3(acc[j2 * 2],     ah, al, bh_[0], bh_[2], bl_[0], bl_[2]);
            mma3(acc[j2 * 2 + 1], ah, al, bh_[1], bh_[3], bl_[1], bl_[3]);
        }
    }

    float m0 = -1e30f, m1 = -1e30f;
#pragma unroll
    for (int j = 0; j < 16; j++) {
        m0 = fmaxf(m0, fmaxf(acc[j][0], acc[j][1]));
        m1 = fmaxf(m1, fmaxf(acc[j][2], acc[j][3]));
    }
    m0 = fmaxf(m0, __shfl_xor_sync(0xffffffffu, m0, 1));
    m0 = fmaxf(m0, __shfl_xor_sync(0xffffffffu, m0, 2));
    m1 = fmaxf(m1, __shfl_xor_sync(0xffffffffu, m1, 1));
    m1 = fmaxf(m1, __shfl_xor_sync(0xffffffffu, m1, 2));
    float s0 = 0.f, s1 = 0.f;
#pragma unroll
    for (int j = 0; j < 16; j++) {
        acc[j][0] = expf(acc[j][0] - m0);
        acc[j][1] = expf(acc[j][1] - m0);
        acc[j][2] = expf(acc[j][2] - m1);
        acc[j][3] = expf(acc[j][3] - m1);
        s0 += acc[j][0] + acc[j][1];
        s1 += acc[j][2] + acc[j][3];
    }
    s0 += __shfl_xor_sync(0xffffffffu, s0, 1);
    s0 += __shfl_xor_sync(0xffffffffu, s0, 2);
    s1 += __shfl_xor_sync(0xffffffffu, s1, 1);
    s1 += __shfl_xor_sync(0xffffffffu, s1, 2);
    const float r0s = 1.f / s0, r1s = 1.f / s1;

    const int pr0 = rbase + g, pr1 = pr0 + 8;
#pragma unroll
    for (int j = 0; j < 16; j++) {
        const uint32_t off0 = pr0 * 256 + ((uint32_t)(j ^ (pr0 & 7)) << 4) + 4 * q;
        const uint32_t off1 = pr1 * 256 + ((uint32_t)(j ^ (pr1 & 7)) << 4) + 4 * q;
        uint16_t h0, l0, h1, l1;
        split2(acc[j][0] * r0s, h0, l0); split2(acc[j][1] * r0s, h1, l1);
        STS32(QH + off0, (uint32_t)h0 | ((uint32_t)h1 << 16));
        STS32(QL + off0, (uint32_t)l0 | ((uint32_t)l1 << 16));
        split2(acc[j][2] * r1s, h0, l0); split2(acc[j][3] * r1s, h1, l1);
        STS32(QH + off1, (uint32_t)h0 | ((uint32_t)h1 << 16));
        STS32(QL + off1, (uint32_t)l0 | ((uint32_t)l1 << 16));
    }
    __syncwarp();

    float acc2[16][4];
#pragma unroll
    for (int j = 0; j < 16; j++)
#pragma unroll
        for (int c = 0; c < 4; c++) acc2[j][c] = 0.f;

#pragma unroll
    for (int kk = 0; kk < 8; kk++) {
        const uint32_t ca = ((uint32_t)((2 * kk + l16) ^ (ra & 7)) << 4) + ra * 256;
        uint32_t ah[4], al[4];
        LDSM4(ah[0], ah[1], ah[2], ah[3], QH + ca);
        LDSM4(al[0], al[1], al[2], al[3], QL + ca);
        const int krow = kk * 16 + l8 * 8 + l7;
#pragma unroll
        for (int j2 = 0; j2 < 8; j2++) {
            const int cj = j2 * 2 + l16;
            const uint32_t cb = ((uint32_t)(cj ^ (krow & 7)) << 4) + krow * 256;
            uint32_t vh_[4], vl_[4];
            LDSM4T(vh_[0], vh_[1], vh_[2], vh_[3], VH + cb);
            LDSM4T(vl_[0], vl_[1], vl_[2], vl_[3], VL + cb);
            mma3(acc2[j2 * 2],     ah, al, vh_[0], vh_[1], vl_[0], vl_[1]);
            mma3(acc2[j2 * 2 + 1], ah, al, vh_[2], vh_[3], vl_[2], vl_[3]);
        }
    }

#pragma unroll
    for (int j = 0; j < 16; j++) {
        const int c = j * 8 + 2 * q;
        const size_t o0 = obase + (size_t)(rbase + g) * Ee + c;
        const size_t o1 = o0 + (size_t)8 * Ee;
        uint16_t h0, l0, h1, l1;
        split2(acc2[j][0], h0, l0); split2(acc2[j][1], h1, l1);
        *(uint32_t*)(Oh + o0) = (uint32_t)h0 | ((uint32_t)h1 << 16);
        *(uint32_t*)(Ol + o0) = (uint32_t)l0 | ((uint32_t)l1 << 16);
        split2(acc2[j][2], h0, l0); split2(acc2[j][3], h1, l1);
        *(uint32_t*)(Oh + o1) = (uint32_t)h0 | ((uint32_t)h1 << 16);
        *(uint32_t*)(Ol + o1) = (uint32_t)l0 | ((uint32_t)l1 << 16);
    }
}

// ---------------------------------------------------------------------------
// launch
// ---------------------------------------------------------------------------
extern "C" void kernel_launch(void* const* d_in, const int* in_sizes, int n_in,
                              void* d_out, int out_size) {
    (void)in_sizes; (void)n_in; (void)out_size;

    const float* x  = (const float*)d_in[0];
    const float* wq = (const float*)d_in[1];
    const float* bq = (const float*)d_in[2];
    const float* wk = (const float*)d_in[3];
    const float* bk = (const float*)d_in[4];
    const float* wv = (const float*)d_in[5];
    const float* bv = (const float*)d_in[6];
    const float* wo = (const float*)d_in[7];
    const float* bo = (const float*)d_in[8];
    const float* w1 = (const float*)d_in[9];
    const float* b1 = (const float*)d_in[10];
    const float* w2 = (const float*)d_in[11];
    const float* b2 = (const float*)d_in[12];
    float* out = (float*)d_out;

    uint16_t *xh, *xl, *qh, *ql, *ath, *atl, *x1h, *x1l, *hh, *hl;
    uint16_t *wqkvh, *wqkvl, *woh, *wol, *w1h, *w1l, *w2h, *w2l;
    float *x1f, *bqkv;
    cudaGetSymbolAddress((void**)&xh, g_xh);     cudaGetSymbolAddress((void**)&xl, g_xl);
    cudaGetSymbolAddress((void**)&qh, g_qh);     cudaGetSymbolAddress((void**)&ql, g_ql);
    cudaGetSymbolAddress((void**)&ath, g_ath);   cudaGetSymbolAddress((void**)&atl, g_atl);
    cudaGetSymbolAddress((void**)&x1f, g_x1f);
    cudaGetSymbolAddress((void**)&x1h, g_x1h);   cudaGetSymbolAddress((void**)&x1l, g_x1l);
    cudaGetSymbolAddress((void**)&hh, g_hh);     cudaGetSymbolAddress((void**)&hl, g_hl);
    cudaGetSymbolAddress((void**)&wqkvh, g_wqkvh); cudaGetSymbolAddress((void**)&wqkvl, g_wqkvl);
    cudaGetSymbolAddress((void**)&woh, g_woh);   cudaGetSymbolAddress((void**)&wol, g_wol);
    cudaGetSymbolAddress((void**)&w1h, g_w1h);   cudaGetSymbolAddress((void**)&w1l, g_w1l);
    cudaGetSymbolAddress((void**)&w2h, g_w2h);   cudaGetSymbolAddress((void**)&w2l, g_w2l);
    cudaGetSymbolAddress((void**)&bqkv, g_bqkv);

    cudaFuncSetAttribute(gemm_p<0>, cudaFuncAttributeMaxDynamicSharedMemorySize, SMEM_G);
    cudaFuncSetAttribute(gemm_p<1>, cudaFuncAttributeMaxDynamicSharedMemorySize, SMEM_G);
    cudaFuncSetAttribute(gemm_p<2>, cudaFuncAttributeMaxDynamicSharedMemorySize, SMEM_G);
    cudaFuncSetAttribute(gemm_p<3>, cudaFuncAttributeMaxDynamicSharedMemorySize, SMEM_G);
    cudaFuncSetAttribute(attn_kernel, cudaFuncAttributeMaxDynamicSharedMemorySize, SMEM_ATTN);

    // 0: merged prep
    prep_all<<<15366, 256>>>(x, bq, bk, bv, wq, wk, wv, wo, w1, w2);
    // 1: fused QKV projection -> planes   (N=1536/256 x M=49152/128)
    gemm_p<0><<<dim3(6, 384), 512, SMEM_G>>>(xh, xl, wqkvh, wqkvl, bqkv, nullptr,
                                             nullptr, qh, ql, NQKV, Ee);
    // 2: attention -> planes
    attn_kernel<<<Bb * Hh, 256, SMEM_ATTN>>>(qh, ql, ath, atl);
    // 3: x1 = x + attn @ wo + bo  (f32 + planes)
    gemm_p<1><<<dim3(2, 384), 512, SMEM_G>>>(ath, atl, woh, wol, bo, x,
                                             x1f, x1h, x1l, Ee, Ee);
    // 4: h = relu(x1 @ w1 + b1)   (planes)
    gemm_p<2><<<dim3(8, 384), 512, SMEM_G>>>(x1h, x1l, w1h, w1l, b1, nullptr,
                                             nullptr, hh, hl, Ff, Ee);
    // 5: out = x1 + h @ w2 + b2   (f32 final)
    gemm_p<3><<<dim3(2, 384), 512, SMEM_G>>>(hh, hl, w2h, w2l, b2, x1f,
                                             out, nullptr, nullptr, Ee, Ff);
}

// round 8
// speedup vs baseline: 1.0071x; 1.0071x over previous
#include <cuda_runtime.h>
#include <cstdint>

// ---------------------------------------------------------------------------
// Transformer block, bf16x3 split-precision mma.sync GEMMs.
// R8: non-volatile MMA asm + term-major passes (32-wide HMMA ILP, no same-acc
// chains). 256-thread CTAs, tile 256x128. Numerics identical to R4-R7.
// B=384, S=128, E=512, H=4, D=128, F=2048.
// ---------------------------------------------------------------------------

constexpr int Bb = 384, Ss = 128, Ee = 512, Hh = 4, Ff = 2048;
constexpr int MM   = Bb * Ss;          // 49152
constexpr int NQKV = 3 * Ee;           // 1536

// -------------------- scratch (static device arrays) -----------------------
__device__ uint16_t g_xh [(size_t)MM * Ee], g_xl [(size_t)MM * Ee];
__device__ uint16_t g_qh [(size_t)MM * NQKV], g_ql [(size_t)MM * NQKV];
__device__ uint16_t g_ath[(size_t)MM * Ee], g_atl[(size_t)MM * Ee];
__device__ float    g_x1f[(size_t)MM * Ee];
__device__ uint16_t g_x1h[(size_t)MM * Ee], g_x1l[(size_t)MM * Ee];
__device__ uint16_t g_hh [(size_t)MM * Ff], g_hl [(size_t)MM * Ff];
__device__ uint16_t g_wqkvh[(size_t)NQKV * Ee], g_wqkvl[(size_t)NQKV * Ee];
__device__ uint16_t g_woh[(size_t)Ee * Ee],  g_wol[(size_t)Ee * Ee];
__device__ uint16_t g_w1h[(size_t)Ff * Ee],  g_w1l[(size_t)Ff * Ee];
__device__ uint16_t g_w2h[(size_t)Ee * Ff],  g_w2l[(size_t)Ee * Ff];
__device__ float    g_bqkv[NQKV];

// -------------------- helpers ----------------------------------------------
__device__ __forceinline__ void split2(float v, uint16_t& h, uint16_t& l) {
    float hf;
    asm("cvt.rn.bf16.f32 %0, %1;" : "=h"(h) : "f"(v));
    asm("cvt.f32.bf16 %0, %1;"    : "=f"(hf) : "h"(h));
    asm("cvt.rn.bf16.f32 %0, %1;" : "=h"(l) : "f"(v - hf));
}
__device__ __forceinline__ uint32_t cvta_s(const void* p) {
    uint32_t a;
    asm("{\n\t.reg .u64 t;\n\tcvta.to.shared.u64 t, %1;\n\tcvt.u32.u64 %0, t;\n\t}"
        : "=r"(a) : "l"(p));
    return a;
}

#define CP16(s, g)  asm volatile("cp.async.cg.shared.global [%0], [%1], 16;" ::"r"(s), "l"(g))
#define CPCOMMIT()  asm volatile("cp.async.commit_group;" ::: "memory")

__device__ __forceinline__ void cpwait(int n) {
    if (n >= 2)      asm volatile("cp.async.wait_group 2;" ::: "memory");
    else if (n == 1) asm volatile("cp.async.wait_group 1;" ::: "memory");
    else             asm volatile("cp.async.wait_group 0;" ::: "memory");
}

#define LDSM4(r0, r1, r2, r3, a) \
    asm volatile("ldmatrix.sync.aligned.m8n8.x4.shared.b16 {%0,%1,%2,%3}, [%4];" \
        : "=r"(r0), "=r"(r1), "=r"(r2), "=r"(r3) : "r"(a))
#define LDSM4T(r0, r1, r2, r3, a) \
    asm volatile("ldmatrix.sync.aligned.m8n8.x4.trans.shared.b16 {%0,%1,%2,%3}, [%4];" \
        : "=r"(r0), "=r"(r1), "=r"(r2), "=r"(r3) : "r"(a))
#define STS32(a, v) asm volatile("st.shared.b32 [%0], %1;" ::"r"(a), "r"(v) : "memory")

// NOTE: non-volatile — deps are fully register-expressed; ptxas may reorder.
__device__ __forceinline__ void mma16(float* d, const uint32_t* a,
                                      uint32_t b0, uint32_t b1) {
    asm("mma.sync.aligned.m16n8k16.row.col.f32.bf16.bf16.f32 "
        "{%0,%1,%2,%3}, {%4,%5,%6,%7}, {%8,%9}, {%0,%1,%2,%3};\n"
        : "+f"(d[0]), "+f"(d[1]), "+f"(d[2]), "+f"(d[3])
        : "r"(a[0]), "r"(a[1]), "r"(a[2]), "r"(a[3]), "r"(b0), "r"(b1));
}
__device__ __forceinline__ void mma3(float* d, const uint32_t* ah, const uint32_t* al,
                                     uint32_t bh0, uint32_t bh1,
                                     uint32_t bl0, uint32_t bl1) {
    mma16(d, ah, bh0, bh1);
    mma16(d, al, bh0, bh1);
    mma16(d, ah, bl0, bl1);
}

// ---------------------------------------------------------------------------
// merged prep: split x + concat bias + transpose/split all weights
// ---------------------------------------------------------------------------
__global__ void prep_all(const float* __restrict__ x,
                         const float* __restrict__ bq, const float* __restrict__ bk,
                         const float* __restrict__ bv,
                         const float* __restrict__ wq, const float* __restrict__ wk,
                         const float* __restrict__ wv, const float* __restrict__ wo,
                         const float* __restrict__ w1, const float* __restrict__ w2) {
    __shared__ uint32_t tile[32][33];
    const int bidx = blockIdx.x;
    if (bidx < 12288) {
        const size_t base = ((size_t)bidx * 256 + threadIdx.x) * 8;
        const float4 v0 = *(const float4*)(x + base);
        const float4 v1 = *(const float4*)(x + base + 4);
        uint16_t h[8], l[8];
        split2(v0.x, h[0], l[0]); split2(v0.y, h[1], l[1]);
        split2(v0.z, h[2], l[2]); split2(v0.w, h[3], l[3]);
        split2(v1.x, h[4], l[4]); split2(v1.y, h[5], l[5]);
        split2(v1.z, h[6], l[6]); split2(v1.w, h[7], l[7]);
        uint4 oh, ol;
        oh.x = h[0] | (h[1] << 16); oh.y = h[2] | (h[3] << 16);
        oh.z = h[4] | (h[5] << 16); oh.w = h[6] | (h[7] << 16);
        ol.x = l[0] | (l[1] << 16); ol.y = l[2] | (l[3] << 16);
        ol.z = l[4] | (l[5] << 16); ol.w = l[6] | (l[7] << 16);
        *(uint4*)(g_xh + base) = oh;
        *(uint4*)(g_xl + base) = ol;
        return;
    }
    if (bidx < 12294) {
        const int i = (bidx - 12288) * 256 + threadIdx.x;
        if (i < NQKV)
            g_bqkv[i] = i < 512 ? bq[i] : (i < 1024 ? bk[i - 512] : bv[i - 1024]);
        return;
    }
    const int id = bidx - 12294;
    const float* W; uint16_t *Dh, *Dl;
    int Nsrc, Kd, tx, ty, rowoff = 0;
    if (id < 768) {
        const int w = id >> 8, loc = id & 255;
        tx = loc & 15; ty = loc >> 4;
        W = w == 0 ? wq : (w == 1 ? wk : wv);
        Dh = g_wqkvh; Dl = g_wqkvl; Nsrc = 512; Kd = 512; rowoff = w * 512;
    } else if (id < 1024) {
        const int loc = id - 768; tx = loc & 15; ty = loc >> 4;
        W = wo; Dh = g_woh; Dl = g_wol; Nsrc = 512; Kd = 512;
    } else if (id < 2048) {
        const int loc = id - 1024; tx = loc & 63; ty = loc >> 6;
        W = w1; Dh = g_w1h; Dl = g_w1l; Nsrc = 2048; Kd = 512;
    } else {
        const int loc = id - 2048; tx = loc & 15; ty = loc >> 4;
        W = w2; Dh = g_w2h; Dl = g_w2l; Nsrc = 512; Kd = 2048;
    }
    const int kb = ty * 32, nb = tx * 32;
    const int lx = threadIdx.x & 31, ly = threadIdx.x >> 5;
    for (int j = ly; j < 32; j += 8) {
        uint16_t h, l;
        split2(W[(size_t)(kb + j) * Nsrc + nb + lx], h, l);
        tile[j][lx] = (uint32_t)h | ((uint32_t)l << 16);
    }
    __syncthreads();
    for (int j = ly; j < 32; j += 8) {
        const uint32_t u = tile[lx][j];
        const size_t o = (size_t)(rowoff + nb + j) * Kd + kb + lx;
        Dh[o] = (uint16_t)u;
        Dl[o] = (uint16_t)(u >> 16);
    }
}

// ---------------------------------------------------------------------------
// GEMM: C = epi(A[M,K] @ B[N,K]^T + bias [, res]), bf16x3 via ldmatrix+HMMA.
// CTA: 256 threads, tile 256(M)x128(N), BK=32, 4-stage cp.async.
// Per k16-half: load ALL fragments (16 LDSM), then 3 term-major passes of
// 32 independent HMMAs each (hh, lh, hl) — per-acc FP order unchanged.
// EPI: 0 = planes; 1 = +res, f32+planes; 2 = relu, planes; 3 = +res, f32.
// ---------------------------------------------------------------------------
constexpr int ST   = 4;
constexpr int A_BYTES = 256 * 128;       // 32768
constexpr int B_OFF   = A_BYTES;
constexpr int STGB    = A_BYTES + 128 * 128;   // 49152
constexpr int SMEM_G  = ST * STGB;       // 196608

template <int EPI>
__device__ __forceinline__ void epi2(float* __restrict__ Cf,
                                     uint16_t* __restrict__ Ch, uint16_t* __restrict__ Cl,
                                     const float* __restrict__ bias,
                                     const float* __restrict__ res,
                                     int r, int c, int N, float v0, float v1) {
    v0 += bias[c]; v1 += bias[c + 1];
    if (EPI == 1 || EPI == 3) {
        const float2 rv = *(const float2*)(res + (size_t)r * N + c);
        v0 += rv.x; v1 += rv.y;
    }
    if (EPI == 2) { v0 = fmaxf(v0, 0.f); v1 = fmaxf(v1, 0.f); }
    if (EPI == 1 || EPI == 3)
        *(float2*)(Cf + (size_t)r * N + c) = make_float2(v0, v1);
    if (EPI != 3) {
        uint16_t h0, l0, h1, l1;
        split2(v0, h0, l0); split2(v1, h1, l1);
        *(uint32_t*)(Ch + (size_t)r * N + c) = (uint32_t)h0 | ((uint32_t)h1 << 16);
        *(uint32_t*)(Cl + (size_t)r * N + c) = (uint32_t)l0 | ((uint32_t)l1 << 16);
    }
}

template <int EPI>
__global__ __launch_bounds__(256, 1)
void gemm_p(const uint16_t* __restrict__ Ah_, const uint16_t* __restrict__ Al_,
            const uint16_t* __restrict__ Bh_, const uint16_t* __restrict__ Bl_,
            const float* __restrict__ bias, const float* __restrict__ res,
            float* __restrict__ Cf,
            uint16_t* __restrict__ Ch, uint16_t* __restrict__ Cl,
            int Nout, int K) {
    extern __shared__ char smraw[];
    const uint32_t sb = cvta_s(smraw);

    const int tid = threadIdx.x, wid = tid >> 5, lane = tid & 31;
    const int wm = wid >> 1, wn = wid & 1;         // 4(M) x 2(N) warp grid
    const int mB = blockIdx.y * 256, nB = blockIdx.x * 128;
    const int l7 = lane & 7, l8 = (lane >> 3) & 1, l16 = lane >> 4;

    // per-thread load geometry
    const int trow = tid >> 3, tch = tid & 7;
    const int kofs = (tch & 3) * 8;
    const uint32_t dA0 = trow * 128 + (((uint32_t)tch ^ (trow & 7)) << 4);
    const uint32_t dB0 = B_OFF + dA0;
    const uint16_t* gA = (tch < 4 ? Ah_ : Al_) + (size_t)(mB + trow) * K + kofs;
    const uint16_t* gB = (tch < 4 ? Bh_ : Bl_) + (size_t)(nB + trow) * K + kofs;
    const size_t aStep = (size_t)32 * K;

    float acc[4][8][4];
#pragma unroll
    for (int a = 0; a < 4; a++)
#pragma unroll
        for (int b = 0; b < 8; b++)
#pragma unroll
            for (int c = 0; c < 4; c++) acc[a][b][c] = 0.f;

    auto issue = [&](int s) {
        const uint32_t stb = sb + (s & (ST - 1)) * STGB;
        const uint16_t* ga = gA + (size_t)s * 32;
        const uint16_t* gb = gB + (size_t)s * 32;
#pragma unroll
        for (int i = 0; i < 8; i++)
            CP16(stb + dA0 + i * 4096, ga + (size_t)i * aStep);
#pragma unroll
        for (int i = 0; i < 4; i++)
            CP16(stb + dB0 + i * 4096, gb + (size_t)i * aStep);
        CPCOMMIT();
    };

    const int nT = K >> 5;
    for (int s = 0; s < ST - 1 && s < nT; s++) issue(s);

    const uint32_t raBase[4] = {
        (uint32_t)(wm * 64 + 0 * 16 + l8 * 8 + l7),
        (uint32_t)(wm * 64 + 1 * 16 + l8 * 8 + l7),
        (uint32_t)(wm * 64 + 2 * 16 + l8 * 8 + l7),
        (uint32_t)(wm * 64 + 3 * 16 + l8 * 8 + l7)};
    const uint32_t rbBase[4] = {
        (uint32_t)(wn * 64 + 0 * 16 + l8 * 8 + l7),
        (uint32_t)(wn * 64 + 1 * 16 + l8 * 8 + l7),
        (uint32_t)(wn * 64 + 2 * 16 + l8 * 8 + l7),
        (uint32_t)(wn * 64 + 3 * 16 + l8 * 8 + l7)};

    for (int t = 0; t < nT; t++) {
        const int rem = nT - 1 - t;
        cpwait(rem < 2 ? rem : 2);
        __syncthreads();
        if (t + ST - 1 < nT) issue(t + ST - 1);

        const uint32_t stb = sb + (t & (ST - 1)) * STGB;
#pragma unroll
        for (int h = 0; h < 2; h++) {
            // ---- load ALL fragments for this k16-half ----
            uint32_t ah[4][4], al[4][4];
#pragma unroll
            for (int mi = 0; mi < 4; mi++) {
                const uint32_t r = raBase[mi];
                const uint32_t base = stb + r * 128;
                const uint32_t ch = (uint32_t)(2 * h + l16) ^ (r & 7);
                const uint32_t cl = (uint32_t)(4 + 2 * h + l16) ^ (r & 7);
                LDSM4(ah[mi][0], ah[mi][1], ah[mi][2], ah[mi][3], base + (ch << 4));
                LDSM4(al[mi][0], al[mi][1], al[mi][2], al[mi][3], base + (cl << 4));
            }
            uint32_t bhm[4][4], blm[4][4];
#pragma unroll
            for (int j2 = 0; j2 < 4; j2++) {
                const uint32_t r = rbBase[j2];
                const uint32_t base = stb + B_OFF + r * 128;
                const uint32_t ch = (uint32_t)(2 * h + l16) ^ (r & 7);
                const uint32_t cl = (uint32_t)(4 + 2 * h + l16) ^ (r & 7);
                LDSM4(bhm[j2][0], bhm[j2][1], bhm[j2][2], bhm[j2][3], base + (ch << 4));
                LDSM4(blm[j2][0], blm[j2][1], blm[j2][2], blm[j2][3], base + (cl << 4));
            }
            // ---- pass 1: Ah x Bh (32 independent HMMAs) ----
#pragma unroll
            for (int j2 = 0; j2 < 4; j2++)
#pragma unroll
                for (int mi = 0; mi < 4; mi++)
#pragma unroll
                    for (int jj = 0; jj < 2; jj++)
                        mma16(acc[mi][2 * j2 + jj], ah[mi],
                              bhm[j2][jj], bhm[j2][2 + jj]);
            // ---- pass 2: Al x Bh ----
#pragma unroll
            for (int j2 = 0; j2 < 4; j2++)
#pragma unroll
                for (int mi = 0; mi < 4; mi++)
#pragma unroll
                    for (int jj = 0; jj < 2; jj++)
                        mma16(acc[mi][2 * j2 + jj], al[mi],
                              bhm[j2][jj], bhm[j2][2 + jj]);
            // ---- pass 3: Ah x Bl ----
#pragma unroll
            for (int j2 = 0; j2 < 4; j2++)
#pragma unroll
                for (int mi = 0; mi < 4; mi++)
#pragma unroll
                    for (int jj = 0; jj < 2; jj++)
                        mma16(acc[mi][2 * j2 + jj], ah[mi],
                              blm[j2][jj], blm[j2][2 + jj]);
        }
    }

    // epilogue
#pragma unroll
    for (int mi = 0; mi < 4; mi++) {
        const int r0 = mB + wm * 64 + mi * 16 + (lane >> 2);
#pragma unroll
        for (int nj = 0; nj < 8; nj++) {
            const int c = nB + wn * 64 + nj * 8 + 2 * (lane & 3);
            epi2<EPI>(Cf, Ch, Cl, bias, res, r0,     c, Nout,
                      acc[mi][nj][0], acc[mi][nj][1]);
            epi2<EPI>(Cf, Ch, Cl, bias, res, r0 + 8, c, Nout,
                      acc[mi][nj][2], acc[mi][nj][3]);
        }
    }
}

// ---------------------------------------------------------------------------
// Attention on bf16 planes (structure as R6; benefits from non-volatile mma).
// ---------------------------------------------------------------------------
constexpr int SMEM_ATTN = 6 * 32768;     // 196608

__global__ __launch_bounds__(256, 1)
void attn_kernel(const uint16_t* __restrict__ qh, const uint16_t* __restrict__ ql,
                 uint16_t* __restrict__ Oh, uint16_t* __restrict__ Ol) {
    extern __shared__ char smraw[];
    const uint32_t sb = cvta_s(smraw);
    const uint32_t QH = sb, QL = sb + 32768, KH = sb + 65536, KL = sb + 98304;
    const uint32_t VH = sb + 131072, VL = sb + 163840;

    const int tid = threadIdx.x;
    const int bh  = blockIdx.x;
    const int bb = bh >> 2, head = bh & 3;
    const size_t rowbase = (size_t)bb * Ss * NQKV;
    const int coloff = head * 128;
    const size_t obase = (size_t)bb * Ss * Ee + (size_t)coloff;

#pragma unroll
    for (int i = 0; i < 48; i++) {
        const int idx = tid + i * 256;
        const int p = idx >> 11;
        const int rem = idx & 2047;
        const int row = rem >> 4, c = rem & 15;
        const uint16_t* base = (p & 1) ? ql : qh;
        const size_t src = rowbase + (size_t)row * NQKV + (p >> 1) * 512 + coloff + c * 8;
        const uint32_t dst = sb + p * 32768 + row * 256 + ((uint32_t)(c ^ (row & 7)) << 4);
        CP16(dst, base + src);
    }
    CPCOMMIT();
    cpwait(0);
    __syncthreads();

    const int wid = tid >> 5, lane = tid & 31;
    const int g = lane >> 2, q = lane & 3;
    const int l7 = lane & 7, l8 = (lane >> 3) & 1, l16 = lane >> 4;
    const int rbase = wid * 16;
    const int ra = rbase + l8 * 8 + l7;

    float acc[16][4];
#pragma unroll
    for (int j = 0; j < 16; j++)
#pragma unroll
        for (int c = 0; c < 4; c++) acc[j][c] = 0.f;

#pragma unroll
    for (int kk = 0; kk < 8; kk++) {
        const uint32_t ca = ((uint32_t)((2 * kk + l16) ^ (ra & 7)) << 4) + ra * 256;
        uint32_t ah[4], al[4];
        LDSM4(ah[0], ah[1], ah[2], ah[3], QH + ca);
        LDSM4(al[0], al[1], al[2], al[3], QL + ca);
#pragma unroll
        for (int j2 = 0; j2 < 8; j2++) {
            const int rb = j2 * 16 + l8 * 8 + l7;
            const uint32_t cb = ((uint32_t)((2 * kk + l16) ^ (rb & 7)) << 4) + rb * 256;
            uint32_t bh_[4], bl_[4];
            LDSM4(bh_[0], bh_[1], bh_[2], bh_[3], KH + cb);
            LDSM4(bl_[0], bl_[1], bl_[2], bl_[3], KL + cb);
            mma3(acc[j2 * 2],     ah, al, bh_[0], bh_[2], bl_[0], bl_[2]);
            mma3(acc[j2 * 2 + 1], ah, al, bh_[1], bh_[3], bl_[1], bl_[3]);
        }
    }

    float m0 = -1e30f, m1 = -1e30f;
#pragma unroll
    for (int j = 0; j < 16; j++) {
        m0 = fmaxf(m0, fmaxf(acc[j][0], acc[j][1]));
        m1 = fmaxf(m1, fmaxf(acc[j][2], acc[j][3]));
    }
    m0 = fmaxf(m0, __shfl_xor_sync(0xffffffffu, m0, 1));
    m0 = fmaxf(m0, __shfl_xor_sync(0xffffffffu, m0, 2));
    m1 = fmaxf(m1, __shfl_xor_sync(0xffffffffu, m1, 1));
    m1 = fmaxf(m1, __shfl_xor_sync(0xffffffffu, m1, 2));
    float s0 = 0.f, s1 = 0.f;
#pragma unroll
    for (int j = 0; j < 16; j++) {
        acc[j][0] = expf(acc[j][0] - m0);
        acc[j][1] = expf(acc[j][1] - m0);
        acc[j][2] = expf(acc[j][2] - m1);
        acc[j][3] = expf(acc[j][3] - m1);
        s0 += acc[j][0] + acc[j][1];
        s1 += acc[j][2] + acc[j][3];
    }
    s0 += __shfl_xor_sync(0xffffffffu, s0, 1);
    s0 += __shfl_xor_sync(0xffffffffu, s0, 2);
    s1 += __shfl_xor_sync(0xffffffffu, s1, 1);
    s1 += __shfl_xor_sync(0xffffffffu, s1, 2);
    const float r0s = 1.f / s0, r1s = 1.f / s1;

    const int pr0 = rbase + g, pr1 = pr0 + 8;
#pragma unroll
    for (int j = 0; j < 16; j++) {
        const uint32_t off0 = pr0 * 256 + ((uint32_t)(j ^ (pr0 & 7)) << 4) + 4 * q;
        const uint32_t off1 = pr1 * 256 + ((uint32_t)(j ^ (pr1 & 7)) << 4) + 4 * q;
        uint16_t h0, l0, h1, l1;
        split2(acc[j][0] * r0s, h0, l0); split2(acc[j][1] * r0s, h1, l1);
        STS32(QH + off0, (uint32_t)h0 | ((uint32_t)h1 << 16));
        STS32(QL + off0, (uint32_t)l0 | ((uint32_t)l1 << 16));
        split2(acc[j][2] * r1s, h0, l0); split2(acc[j][3] * r1s, h1, l1);
        STS32(QH + off1, (uint32_t)h0 | ((uint32_t)h1 << 16));
        STS32(QL + off1, (uint32_t)l0 | ((uint32_t)l1 << 16));
    }
    __syncwarp();

    float acc2[16][4];
#pragma unroll
    for (int j = 0; j < 16; j++)
#pragma unroll
        for (int c = 0; c < 4; c++) acc2[j][c] = 0.f;

#pragma unroll
    for (int kk = 0; kk < 8; kk++) {
        const uint32_t ca = ((uint32_t)((2 * kk + l16) ^ (ra & 7)) << 4) + ra * 256;
        uint32_t ah[4], al[4];
        LDSM4(ah[0], ah[1], ah[2], ah[3], QH + ca);
        LDSM4(al[0], al[1], al[2], al[3], QL + ca);
        const int krow = kk * 16 + l8 * 8 + l7;
#pragma unroll
        for (int j2 = 0; j2 < 8; j2++) {
            const int cj = j2 * 2 + l16;
            const uint32_t cb = ((uint32_t)(cj ^ (krow & 7)) << 4) + krow * 256;
            uint32_t vh_[4], vl_[4];
            LDSM4T(vh_[0], vh_[1], vh_[2], vh_[3], VH + cb);
            LDSM4T(vl_[0], vl_[1], vl_[2], vl_[3], VL + cb);
            mma3(acc2[j2 * 2],     ah, al, vh_[0], vh_[1], vl_[0], vl_[1]);
            mma3(acc2[j2 * 2 + 1], ah, al, vh_[2], vh_[3], vl_[2], vl_[3]);
        }
    }

#pragma unroll
    for (int j = 0; j < 16; j++) {
        const int c = j * 8 + 2 * q;
        const size_t o0 = obase + (size_t)(rbase + g) * Ee + c;
        const size_t o1 = o0 + (size_t)8 * Ee;
        uint16_t h0, l0, h1, l1;
        split2(acc2[j][0], h0, l0); split2(acc2[j][1], h1, l1);
        *(uint32_t*)(Oh + o0) = (uint32_t)h0 | ((uint32_t)h1 << 16);
        *(uint32_t*)(Ol + o0) = (uint32_t)l0 | ((uint32_t)l1 << 16);
        split2(acc2[j][2], h0, l0); split2(acc2[j][3], h1, l1);
        *(uint32_t*)(Oh + o1) = (uint32_t)h0 | ((uint32_t)h1 << 16);
        *(uint32_t*)(Ol + o1) = (uint32_t)l0 | ((uint32_t)l1 << 16);
    }
}

// ---------------------------------------------------------------------------
// launch
// ---------------------------------------------------------------------------
extern "C" void kernel_launch(void* const* d_in, const int* in_sizes, int n_in,
                              void* d_out, int out_size) {
    (void)in_sizes; (void)n_in; (void)out_size;

    const float* x  = (const float*)d_in[0];
    const float* wq = (const float*)d_in[1];
    const float* bq = (const float*)d_in[2];
    const float* wk = (const float*)d_in[3];
    const float* bk = (const float*)d_in[4];
    const float* wv = (const float*)d_in[5];
    const float* bv = (const float*)d_in[6];
    const float* wo = (const float*)d_in[7];
    const float* bo = (const float*)d_in[8];
    const float* w1 = (const float*)d_in[9];
    const float* b1 = (const float*)d_in[10];
    const float* w2 = (const float*)d_in[11];
    const float* b2 = (const float*)d_in[12];
    float* out = (float*)d_out;

    uint16_t *xh, *xl, *qh, *ql, *ath, *atl, *x1h, *x1l, *hh, *hl;
    uint16_t *wqkvh, *wqkvl, *woh, *wol, *w1h, *w1l, *w2h, *w2l;
    float *x1f, *bqkv;
    cudaGetSymbolAddress((void**)&xh, g_xh);     cudaGetSymbolAddress((void**)&xl, g_xl);
    cudaGetSymbolAddress((void**)&qh, g_qh);     cudaGetSymbolAddress((void**)&ql, g_ql);
    cudaGetSymbolAddress((void**)&ath, g_ath);   cudaGetSymbolAddress((void**)&atl, g_atl);
    cudaGetSymbolAddress((void**)&x1f, g_x1f);
    cudaGetSymbolAddress((void**)&x1h, g_x1h);   cudaGetSymbolAddress((void**)&x1l, g_x1l);
    cudaGetSymbolAddress((void**)&hh, g_hh);     cudaGetSymbolAddress((void**)&hl, g_hl);
    cudaGetSymbolAddress((void**)&wqkvh, g_wqkvh); cudaGetSymbolAddress((void**)&wqkvl, g_wqkvl);
    cudaGetSymbolAddress((void**)&woh, g_woh);   cudaGetSymbolAddress((void**)&wol, g_wol);
    cudaGetSymbolAddress((void**)&w1h, g_w1h);   cudaGetSymbolAddress((void**)&w1l, g_w1l);
    cudaGetSymbolAddress((void**)&w2h, g_w2h);   cudaGetSymbolAddress((void**)&w2l, g_w2l);
    cudaGetSymbolAddress((void**)&bqkv, g_bqkv);

    cudaFuncSetAttribute(gemm_p<0>, cudaFuncAttributeMaxDynamicSharedMemorySize, SMEM_G);
    cudaFuncSetAttribute(gemm_p<1>, cudaFuncAttributeMaxDynamicSharedMemorySize, SMEM_G);
    cudaFuncSetAttribute(gemm_p<2>, cudaFuncAttributeMaxDynamicSharedMemorySize, SMEM_G);
    cudaFuncSetAttribute(gemm_p<3>, cudaFuncAttributeMaxDynamicSharedMemorySize, SMEM_G);
    cudaFuncSetAttribute(attn_kernel, cudaFuncAttributeMaxDynamicSharedMemorySize, SMEM_ATTN);

    // 0: merged prep
    prep_all<<<15366, 256>>>(x, bq, bk, bv, wq, wk, wv, wo, w1, w2);
    // 1: fused QKV projection -> planes   (N=1536/128 x M=49152/256)
    gemm_p<0><<<dim3(12, 192), 256, SMEM_G>>>(xh, xl, wqkvh, wqkvl, bqkv, nullptr,
                                              nullptr, qh, ql, NQKV, Ee);
    // 2: attention -> planes
    attn_kernel<<<Bb * Hh, 256, SMEM_ATTN>>>(qh, ql, ath, atl);
    // 3: x1 = x + attn @ wo + bo  (f32 + planes)
    gemm_p<1><<<dim3(4, 192), 256, SMEM_G>>>(ath, atl, woh, wol, bo, x,
                                             x1f, x1h, x1l, Ee, Ee);
    // 4: h = relu(x1 @ w1 + b1)   (planes)
    gemm_p<2><<<dim3(16, 192), 256, SMEM_G>>>(x1h, x1l, w1h, w1l, b1, nullptr,
                                              nullptr, hh, hl, Ff, Ee);
    // 5: out = x1 + h @ w2 + b2   (f32 final)
    gemm_p<3><<<dim3(4, 192), 256, SMEM_G>>>(hh, hl, w2h, w2l, b2, x1f,
                                             out, nullptr, nullptr, Ee, Ff);
}

// round 9
// speedup vs baseline: 1.0078x; 1.0006x over previous
#include <cuda_runtime.h>
#include <cstdint>

// ---------------------------------------------------------------------------
// Transformer block, bf16x3 split-precision mma.sync GEMMs.
// R8: non-volatile MMA asm + term-major passes (32-wide HMMA ILP, no same-acc
// chains). 256-thread CTAs, tile 256x128. Numerics identical to R4-R7.
// B=384, S=128, E=512, H=4, D=128, F=2048.
// ---------------------------------------------------------------------------

constexpr int Bb = 384, Ss = 128, Ee = 512, Hh = 4, Ff = 2048;
constexpr int MM   = Bb * Ss;          // 49152
constexpr int NQKV = 3 * Ee;           // 1536

// -------------------- scratch (static device arrays) -----------------------
__device__ uint16_t g_xh [(size_t)MM * Ee], g_xl [(size_t)MM * Ee];
__device__ uint16_t g_qh [(size_t)MM * NQKV], g_ql [(size_t)MM * NQKV];
__device__ uint16_t g_ath[(size_t)MM * Ee], g_atl[(size_t)MM * Ee];
__device__ float    g_x1f[(size_t)MM * Ee];
__device__ uint16_t g_x1h[(size_t)MM * Ee], g_x1l[(size_t)MM * Ee];
__device__ uint16_t g_hh [(size_t)MM * Ff], g_hl [(size_t)MM * Ff];
__device__ uint16_t g_wqkvh[(size_t)NQKV * Ee], g_wqkvl[(size_t)NQKV * Ee];
__device__ uint16_t g_woh[(size_t)Ee * Ee],  g_wol[(size_t)Ee * Ee];
__device__ uint16_t g_w1h[(size_t)Ff * Ee],  g_w1l[(size_t)Ff * Ee];
__device__ uint16_t g_w2h[(size_t)Ee * Ff],  g_w2l[(size_t)Ee * Ff];
__device__ float    g_bqkv[NQKV];

// -------------------- helpers ----------------------------------------------
__device__ __forceinline__ void split2(float v, uint16_t& h, uint16_t& l) {
    float hf;
    asm("cvt.rn.bf16.f32 %0, %1;" : "=h"(h) : "f"(v));
    asm("cvt.f32.bf16 %0, %1;"    : "=f"(hf) : "h"(h));
    asm("cvt.rn.bf16.f32 %0, %1;" : "=h"(l) : "f"(v - hf));
}
__device__ __forceinline__ uint32_t cvta_s(const void* p) {
    uint32_t a;
    asm("{\n\t.reg .u64 t;\n\tcvta.to.shared.u64 t, %1;\n\tcvt.u32.u64 %0, t;\n\t}"
        : "=r"(a) : "l"(p));
    return a;
}

#define CP16(s, g)  asm volatile("cp.async.cg.shared.global [%0], [%1], 16;" ::"r"(s), "l"(g))
#define CPCOMMIT()  asm volatile("cp.async.commit_group;" ::: "memory")

__device__ __forceinline__ void cpwait(int n) {
    if (n >= 2)      asm volatile("cp.async.wait_group 2;" ::: "memory");
    else if (n == 1) asm volatile("cp.async.wait_group 1;" ::: "memory");
    else             asm volatile("cp.async.wait_group 0;" ::: "memory");
}

#define LDSM4(r0, r1, r2, r3, a) \
    asm volatile("ldmatrix.sync.aligned.m8n8.x4.shared.b16 {%0,%1,%2,%3}, [%4];" \
        : "=r"(r0), "=r"(r1), "=r"(r2), "=r"(r3) : "r"(a))
#define LDSM4T(r0, r1, r2, r3, a) \
    asm volatile("ldmatrix.sync.aligned.m8n8.x4.trans.shared.b16 {%0,%1,%2,%3}, [%4];" \
        : "=r"(r0), "=r"(r1), "=r"(r2), "=r"(r3) : "r"(a))
#define STS32(a, v) asm volatile("st.shared.b32 [%0], %1;" ::"r"(a), "r"(v) : "memory")

// NOTE: non-volatile — deps are fully register-expressed; ptxas may reorder.
__device__ __forceinline__ void mma16(float* d, const uint32_t* a,
                                      uint32_t b0, uint32_t b1) {
    asm("mma.sync.aligned.m16n8k16.row.col.f32.bf16.bf16.f32 "
        "{%0,%1,%2,%3}, {%4,%5,%6,%7}, {%8,%9}, {%0,%1,%2,%3};\n"
        : "+f"(d[0]), "+f"(d[1]), "+f"(d[2]), "+f"(d[3])
        : "r"(a[0]), "r"(a[1]), "r"(a[2]), "r"(a[3]), "r"(b0), "r"(b1));
}
__device__ __forceinline__ void mma3(float* d, const uint32_t* ah, const uint32_t* al,
                                     uint32_t bh0, uint32_t bh1,
                                     uint32_t bl0, uint32_t bl1) {
    mma16(d, ah, bh0, bh1);
    mma16(d, al, bh0, bh1);
    mma16(d, ah, bl0, bl1);
}

// ---------------------------------------------------------------------------
// merged prep: split x + concat bias + transpose/split all weights
// ---------------------------------------------------------------------------
__global__ void prep_all(const float* __restrict__ x,
                         const float* __restrict__ bq, const float* __restrict__ bk,
                         const float* __restrict__ bv,
                         const float* __restrict__ wq, const float* __restrict__ wk,
                         const float* __restrict__ wv, const float* __restrict__ wo,
                         const float* __restrict__ w1, const float* __restrict__ w2) {
    __shared__ uint32_t tile[32][33];
    const int bidx = blockIdx.x;
    if (bidx < 12288) {
        const size_t base = ((size_t)bidx * 256 + threadIdx.x) * 8;
        const float4 v0 = *(const float4*)(x + base);
        const float4 v1 = *(const float4*)(x + base + 4);
        uint16_t h[8], l[8];
        split2(v0.x, h[0], l[0]); split2(v0.y, h[1], l[1]);
        split2(v0.z, h[2], l[2]); split2(v0.w, h[3], l[3]);
        split2(v1.x, h[4], l[4]); split2(v1.y, h[5], l[5]);
        split2(v1.z, h[6], l[6]); split2(v1.w, h[7], l[7]);
        uint4 oh, ol;
        oh.x = h[0] | (h[1] << 16); oh.y = h[2] | (h[3] << 16);
        oh.z = h[4] | (h[5] << 16); oh.w = h[6] | (h[7] << 16);
        ol.x = l[0] | (l[1] << 16); ol.y = l[2] | (l[3] << 16);
        ol.z = l[4] | (l[5] << 16); ol.w = l[6] | (l[7] << 16);
        *(uint4*)(g_xh + base) = oh;
        *(uint4*)(g_xl + base) = ol;
        return;
    }
    if (bidx < 12294) {
        const int i = (bidx - 12288) * 256 + threadIdx.x;
        if (i < NQKV)
            g_bqkv[i] = i < 512 ? bq[i] : (i < 1024 ? bk[i - 512] : bv[i - 1024]);
        return;
    }
    const int id = bidx - 12294;
    const float* W; uint16_t *Dh, *Dl;
    int Nsrc, Kd, tx, ty, rowoff = 0;
    if (id < 768) {
        const int w = id >> 8, loc = id & 255;
        tx = loc & 15; ty = loc >> 4;
        W = w == 0 ? wq : (w == 1 ? wk : wv);
        Dh = g_wqkvh; Dl = g_wqkvl; Nsrc = 512; Kd = 512; rowoff = w * 512;
    } else if (id < 1024) {
        const int loc = id - 768; tx = loc & 15; ty = loc >> 4;
        W = wo; Dh = g_woh; Dl = g_wol; Nsrc = 512; Kd = 512;
    } else if (id < 2048) {
        const int loc = id - 1024; tx = loc & 63; ty = loc >> 6;
        W = w1; Dh = g_w1h; Dl = g_w1l; Nsrc = 2048; Kd = 512;
    } else {
        const int loc = id - 2048; tx = loc & 15; ty = loc >> 4;
        W = w2; Dh = g_w2h; Dl = g_w2l; Nsrc = 512; Kd = 2048;
    }
    const int kb = ty * 32, nb = tx * 32;
    const int lx = threadIdx.x & 31, ly = threadIdx.x >> 5;
    for (int j = ly; j < 32; j += 8) {
        uint16_t h, l;
        split2(W[(size_t)(kb + j) * Nsrc + nb + lx], h, l);
        tile[j][lx] = (uint32_t)h | ((uint32_t)l << 16);
    }
    __syncthreads();
    for (int j = ly; j < 32; j += 8) {
        const uint32_t u = tile[lx][j];
        const size_t o = (size_t)(rowoff + nb + j) * Kd + kb + lx;
        Dh[o] = (uint16_t)u;
        Dl[o] = (uint16_t)(u >> 16);
    }
}

// ---------------------------------------------------------------------------
// GEMM: C = epi(A[M,K] @ B[N,K]^T + bias [, res]), bf16x3 via ldmatrix+HMMA.
// CTA: 256 threads, tile 256(M)x128(N), BK=32, 4-stage cp.async.
// Per k16-half: load ALL fragments (16 LDSM), then 3 term-major passes of
// 32 independent HMMAs each (hh, lh, hl) — per-acc FP order unchanged.
// EPI: 0 = planes; 1 = +res, f32+planes; 2 = relu, planes; 3 = +res, f32.
// ---------------------------------------------------------------------------
constexpr int ST   = 4;
constexpr int A_BYTES = 256 * 128;       // 32768
constexpr int B_OFF   = A_BYTES;
constexpr int STGB    = A_BYTES + 128 * 128;   // 49152
constexpr int SMEM_G  = ST * STGB;       // 196608

template <int EPI>
__device__ __forceinline__ void epi2(float* __restrict__ Cf,
                                     uint16_t* __restrict__ Ch, uint16_t* __restrict__ Cl,
                                     const float* __restrict__ bias,
                                     const float* __restrict__ res,
                                     int r, int c, int N, float v0, float v1) {
    v0 += bias[c]; v1 += bias[c + 1];
    if (EPI == 1 || EPI == 3) {
        const float2 rv = *(const float2*)(res + (size_t)r * N + c);
        v0 += rv.x; v1 += rv.y;
    }
    if (EPI == 2) { v0 = fmaxf(v0, 0.f); v1 = fmaxf(v1, 0.f); }
    if (EPI == 1 || EPI == 3)
        *(float2*)(Cf + (size_t)r * N + c) = make_float2(v0, v1);
    if (EPI != 3) {
        uint16_t h0, l0, h1, l1;
        split2(v0, h0, l0); split2(v1, h1, l1);
        *(uint32_t*)(Ch + (size_t)r * N + c) = (uint32_t)h0 | ((uint32_t)h1 << 16);
        *(uint32_t*)(Cl + (size_t)r * N + c) = (uint32_t)l0 | ((uint32_t)l1 << 16);
    }
}

template <int EPI>
__global__ __launch_bounds__(256, 1)
void gemm_p(const uint16_t* __restrict__ Ah_, const uint16_t* __restrict__ Al_,
            const uint16_t* __restrict__ Bh_, const uint16_t* __restrict__ Bl_,
            const float* __restrict__ bias, const float* __restrict__ res,
            float* __restrict__ Cf,
            uint16_t* __restrict__ Ch, uint16_t* __restrict__ Cl,
            int Nout, int K) {
    extern __shared__ char smraw[];
    const uint32_t sb = cvta_s(smraw);

    const int tid = threadIdx.x, wid = tid >> 5, lane = tid & 31;
    const int wm = wid >> 1, wn = wid & 1;         // 4(M) x 2(N) warp grid
    const int mB = blockIdx.y * 256, nB = blockIdx.x * 128;
    const int l7 = lane & 7, l8 = (lane >> 3) & 1, l16 = lane >> 4;

    // per-thread load geometry
    const int trow = tid >> 3, tch = tid & 7;
    const int kofs = (tch & 3) * 8;
    const uint32_t dA0 = trow * 128 + (((uint32_t)tch ^ (trow & 7)) << 4);
    const uint32_t dB0 = B_OFF + dA0;
    const uint16_t* gA = (tch < 4 ? Ah_ : Al_) + (size_t)(mB + trow) * K + kofs;
    const uint16_t* gB = (tch < 4 ? Bh_ : Bl_) + (size_t)(nB + trow) * K + kofs;
    const size_t aStep = (size_t)32 * K;

    float acc[4][8][4];
#pragma unroll
    for (int a = 0; a < 4; a++)
#pragma unroll
        for (int b = 0; b < 8; b++)
#pragma unroll
            for (int c = 0; c < 4; c++) acc[a][b][c] = 0.f;

    auto issue = [&](int s) {
        const uint32_t stb = sb + (s & (ST - 1)) * STGB;
        const uint16_t* ga = gA + (size_t)s * 32;
        const uint16_t* gb = gB + (size_t)s * 32;
#pragma unroll
        for (int i = 0; i < 8; i++)
            CP16(stb + dA0 + i * 4096, ga + (size_t)i * aStep);
#pragma unroll
        for (int i = 0; i < 4; i++)
            CP16(stb + dB0 + i * 4096, gb + (size_t)i * aStep);
        CPCOMMIT();
    };

    const int nT = K >> 5;
    for (int s = 0; s < ST - 1 && s < nT; s++) issue(s);

    const uint32_t raBase[4] = {
        (uint32_t)(wm * 64 + 0 * 16 + l8 * 8 + l7),
        (uint32_t)(wm * 64 + 1 * 16 + l8 * 8 + l7),
        (uint32_t)(wm * 64 + 2 * 16 + l8 * 8 + l7),
        (uint32_t)(wm * 64 + 3 * 16 + l8 * 8 + l7)};
    const uint32_t rbBase[4] = {
        (uint32_t)(wn * 64 + 0 * 16 + l8 * 8 + l7),
        (uint32_t)(wn * 64 + 1 * 16 + l8 * 8 + l7),
        (uint32_t)(wn * 64 + 2 * 16 + l8 * 8 + l7),
        (uint32_t)(wn * 64 + 3 * 16 + l8 * 8 + l7)};

    for (int t = 0; t < nT; t++) {
        const int rem = nT - 1 - t;
        cpwait(rem < 2 ? rem : 2);
        __syncthreads();
        if (t + ST - 1 < nT) issue(t + ST - 1);

        const uint32_t stb = sb + (t & (ST - 1)) * STGB;
#pragma unroll
        for (int h = 0; h < 2; h++) {
            // ---- load ALL fragments for this k16-half ----
            uint32_t ah[4][4], al[4][4];
#pragma unroll
            for (int mi = 0; mi < 4; mi++) {
                const uint32_t r = raBase[mi];
                const uint32_t base = stb + r * 128;
                const uint32_t ch = (uint32_t)(2 * h + l16) ^ (r & 7);
                const uint32_t cl = (uint32_t)(4 + 2 * h + l16) ^ (r & 7);
                LDSM4(ah[mi][0], ah[mi][1], ah[mi][2], ah[mi][3], base + (ch << 4));
                LDSM4(al[mi][0], al[mi][1], al[mi][2], al[mi][3], base + (cl << 4));
            }
            uint32_t bhm[4][4], blm[4][4];
#pragma unroll
            for (int j2 = 0; j2 < 4; j2++) {
                const uint32_t r = rbBase[j2];
                const uint32_t base = stb + B_OFF + r * 128;
                const uint32_t ch = (uint32_t)(2 * h + l16) ^ (r & 7);
                const uint32_t cl = (uint32_t)(4 + 2 * h + l16) ^ (r & 7);
                LDSM4(bhm[j2][0], bhm[j2][1], bhm[j2][2], bhm[j2][3], base + (ch << 4));
                LDSM4(blm[j2][0], blm[j2][1], blm[j2][2], blm[j2][3], base + (cl << 4));
            }
            // ---- pass 1: Ah x Bh (32 independent HMMAs) ----
#pragma unroll
            for (int j2 = 0; j2 < 4; j2++)
#pragma unroll
                for (int mi = 0; mi < 4; mi++)
#pragma unroll
                    for (int jj = 0; jj < 2; jj++)
                        mma16(acc[mi][2 * j2 + jj], ah[mi],
                              bhm[j2][jj], bhm[j2][2 + jj]);
            // ---- pass 2: Al x Bh ----
#pragma unroll
            for (int j2 = 0; j2 < 4; j2++)
#pragma unroll
                for (int mi = 0; mi < 4; mi++)
#pragma unroll
                    for (int jj = 0; jj < 2; jj++)
                        mma16(acc[mi][2 * j2 + jj], al[mi],
                              bhm[j2][jj], bhm[j2][2 + jj]);
            // ---- pass 3: Ah x Bl ----
#pragma unroll
            for (int j2 = 0; j2 < 4; j2++)
#pragma unroll
                for (int mi = 0; mi < 4; mi++)
#pragma unroll
                    for (int jj = 0; jj < 2; jj++)
                        mma16(acc[mi][2 * j2 + jj], ah[mi],
                              blm[j2][jj], blm[j2][2 + jj]);
        }
    }

    // epilogue
#pragma unroll
    for (int mi = 0; mi < 4; mi++) {
        const int r0 = mB + wm * 64 + mi * 16 + (lane >> 2);
#pragma unroll
        for (int nj = 0; nj < 8; nj++) {
            const int c = nB + wn * 64 + nj * 8 + 2 * (lane & 3);
            epi2<EPI>(Cf, Ch, Cl, bias, res, r0,     c, Nout,
                      acc[mi][nj][0], acc[mi][nj][1]);
            epi2<EPI>(Cf, Ch, Cl, bias, res, r0 + 8, c, Nout,
                      acc[mi][nj][2], acc[mi][nj][3]);
        }
    }
}

// ---------------------------------------------------------------------------
// Attention on bf16 planes (structure as R6; benefits from non-volatile mma).
// ---------------------------------------------------------------------------
constexpr int SMEM_ATTN = 6 * 32768;     // 196608

__global__ __launch_bounds__(256, 1)
void attn_kernel(const uint16_t* __restrict__ qh, const uint16_t* __restrict__ ql,
                 uint16_t* __restrict__ Oh, uint16_t* __restrict__ Ol) {
    extern __shared__ char smraw[];
    const uint32_t sb = cvta_s(smraw);
    const uint32_t QH = sb, QL = sb + 32768, KH = sb + 65536, KL = sb + 98304;
    const uint32_t VH = sb + 131072, VL = sb + 163840;

    const int tid = threadIdx.x;
    const int bh  = blockIdx.x;
    const int bb = bh >> 2, head = bh & 3;
    const size_t rowbase = (size_t)bb * Ss * NQKV;
    const int coloff = head * 128;
    const size_t obase = (size_t)bb * Ss * Ee + (size_t)coloff;

#pragma unroll
    for (int i = 0; i < 48; i++) {
        const int idx = tid + i * 256;
        const int p = idx >> 11;
        const int rem = idx & 2047;
        const int row = rem >> 4, c = rem & 15;
        const uint16_t* base = (p & 1) ? ql : qh;
        const size_t src = rowbase + (size_t)row * NQKV + (p >> 1) * 512 + coloff + c * 8;
        const uint32_t dst = sb + p * 32768 + row * 256 + ((uint32_t)(c ^ (row & 7)) << 4);
        CP16(dst, base + src);
    }
    CPCOMMIT();
    cpwait(0);
    __syncthreads();

    const int wid = tid >> 5, lane = tid & 31;
    const int g = lane >> 2, q = lane & 3;
    const int l7 = lane & 7, l8 = (lane >> 3) & 1, l16 = lane >> 4;
    const int rbase = wid * 16;
    const int ra = rbase + l8 * 8 + l7;

    float acc[16][4];
#pragma unroll
    for (int j = 0; j < 16; j++)
#pragma unroll
        for (int c = 0; c < 4; c++) acc[j][c] = 0.f;

#pragma unroll
    for (int kk = 0; kk < 8; kk++) {
        const uint32_t ca = ((uint32_t)((2 * kk + l16) ^ (ra & 7)) << 4) + ra * 256;
        uint32_t ah[4], al[4];
        LDSM4(ah[0], ah[1], ah[2], ah[3], QH + ca);
        LDSM4(al[0], al[1], al[2], al[3], QL + ca);
#pragma unroll
        for (int j2 = 0; j2 < 8; j2++) {
            const int rb = j2 * 16 + l8 * 8 + l7;
            const uint32_t cb = ((uint32_t)((2 * kk + l16) ^ (rb & 7)) << 4) + rb * 256;
            uint32_t bh_[4], bl_[4];
            LDSM4(bh_[0], bh_[1], bh_[2], bh_[3], KH + cb);
            LDSM4(bl_[0], bl_[1], bl_[2], bl_[3], KL + cb);
            mma3(acc[j2 * 2],     ah, al, bh_[0], bh_[2], bl_[0], bl_[2]);
            mma3(acc[j2 * 2 + 1], ah, al, bh_[1], bh_[3], bl_[1], bl_[3]);
        }
    }

    float m0 = -1e30f, m1 = -1e30f;
#pragma unroll
    for (int j = 0; j < 16; j++) {
        m0 = fmaxf(m0, fmaxf(acc[j][0], acc[j][1]));
        m1 = fmaxf(m1, fmaxf(acc[j][2], acc[j][3]));
    }
    m0 = fmaxf(m0, __shfl_xor_sync(0xffffffffu, m0, 1));
    m0 = fmaxf(m0, __shfl_xor_sync(0xffffffffu, m0, 2));
    m1 = fmaxf(m1, __shfl_xor_sync(0xffffffffu, m1, 1));
    m1 = fmaxf(m1, __shfl_xor_sync(0xffffffffu, m1, 2));
    float s0 = 0.f, s1 = 0.f;
#pragma unroll
    for (int j = 0; j < 16; j++) {
        acc[j][0] = expf(acc[j][0] - m0);
        acc[j][1] = expf(acc[j][1] - m0);
        acc[j][2] = expf(acc[j][2] - m1);
        acc[j][3] = expf(acc[j][3] - m1);
        s0 += acc[j][0] + acc[j][1];
        s1 += acc[j][2] + acc[j][3];
    }
    s0 += __shfl_xor_sync(0xffffffffu, s0, 1);
    s0 += __shfl_xor_sync(0xffffffffu, s0, 2);
    s1 += __shfl_xor_sync(0xffffffffu, s1, 1);
    s1 += __shfl_xor_sync(0xffffffffu, s1, 2);
    const float r0s = 1.f / s0, r1s = 1.f / s1;

    const int pr0 = rbase + g, pr1 = pr0 + 8;
#pragma unroll
    for (int j = 0; j < 16; j++) {
        const uint32_t off0 = pr0 * 256 + ((uint32_t)(j ^ (pr0 & 7)) << 4) + 4 * q;
        const uint32_t off1 = pr1 * 256 + ((uint32_t)(j ^ (pr1 & 7)) << 4) + 4 * q;
        uint16_t h0, l0, h1, l1;
        split2(acc[j][0] * r0s, h0, l0); split2(acc[j][1] * r0s, h1, l1);
        STS32(QH + off0, (uint32_t)h0 | ((uint32_t)h1 << 16));
        STS32(QL + off0, (uint32_t)l0 | ((uint32_t)l1 << 16));
        split2(acc[j][2] * r1s, h0, l0); split2(acc[j][3] * r1s, h1, l1);
        STS32(QH + off1, (uint32_t)h0 | ((uint32_t)h1 << 16));
        STS32(QL + off1, (uint32_t)l0 | ((uint32_t)l1 << 16));
    }
    __syncwarp();

    float acc2[16][4];
#pragma unroll
    for (int j = 0; j < 16; j++)
#pragma unroll
        for (int c = 0; c < 4; c++) acc2[j][c] = 0.f;

#pragma unroll
    for (int kk = 0; kk < 8; kk++) {
        const uint32_t ca = ((uint32_t)((2 * kk + l16) ^ (ra & 7)) << 4) + ra * 256;
        uint32_t ah[4], al[4];
        LDSM4(ah[0], ah[1], ah[2], ah[3], QH + ca);
        LDSM4(al[0], al[1], al[2], al[3], QL + ca);
        const int krow = kk * 16 + l8 * 8 + l7;
#pragma unroll
        for (int j2 = 0; j2 < 8; j2++) {
            const int cj = j2 * 2 + l16;
            const uint32_t cb = ((uint32_t)(cj ^ (krow & 7)) << 4) + krow * 256;
            uint32_t vh_[4], vl_[4];
            LDSM4T(vh_[0], vh_[1], vh_[2], vh_[3], VH + cb);
            LDSM4T(vl_[0], vl_[1], vl_[2], vl_[3], VL + cb);
            mma3(acc2[j2 * 2],     ah, al, vh_[0], vh_[1], vl_[0], vl_[1]);
            mma3(acc2[j2 * 2 + 1], ah, al, vh_[2], vh_[3], vl_[2], vl_[3]);
        }
    }

#pragma unroll
    for (int j = 0; j < 16; j++) {
        const int c = j * 8 + 2 * q;
        const size_t o0 = obase + (size_t)(rbase + g) * Ee + c;
        const size_t o1 = o0 + (size_t)8 * Ee;
        uint16_t h0, l0, h1, l1;
        split2(acc2[j][0], h0, l0); split2(acc2[j][1], h1, l1);
        *(uint32_t*)(Oh + o0) = (uint32_t)h0 | ((uint32_t)h1 << 16);
        *(uint32_t*)(Ol + o0) = (uint32_t)l0 | ((uint32_t)l1 << 16);
        split2(acc2[j][2], h0, l0); split2(acc2[j][3], h1, l1);
        *(uint32_t*)(Oh + o1) = (uint32_t)h0 | ((uint32_t)h1 << 16);
        *(uint32_t*)(Ol + o1) = (uint32_t)l0 | ((uint32_t)l1 << 16);
    }
}

// ---------------------------------------------------------------------------
// launch
// ---------------------------------------------------------------------------
extern "C" void kernel_launch(void* const* d_in, const int* in_sizes, int n_in,
                              void* d_out, int out_size) {
    (void)in_sizes; (void)n_in; (void)out_size;

    const float* x  = (const float*)d_in[0];
    const float* wq = (const float*)d_in[1];
    const float* bq = (const float*)d_in[2];
    const float* wk = (const float*)d_in[3];
    const float* bk = (const float*)d_in[4];
    const float* wv = (const float*)d_in[5];
    const float* bv = (const float*)d_in[6];
    const float* wo = (const float*)d_in[7];
    const float* bo = (const float*)d_in[8];
    const float* w1 = (const float*)d_in[9];
    const float* b1 = (const float*)d_in[10];
    const float* w2 = (const float*)d_in[11];
    const float* b2 = (const float*)d_in[12];
    float* out = (float*)d_out;

    uint16_t *xh, *xl, *qh, *ql, *ath, *atl, *x1h, *x1l, *hh, *hl;
    uint16_t *wqkvh, *wqkvl, *woh, *wol, *w1h, *w1l, *w2h, *w2l;
    float *x1f, *bqkv;
    cudaGetSymbolAddress((void**)&xh, g_xh);     cudaGetSymbolAddress((void**)&xl, g_xl);
    cudaGetSymbolAddress((void**)&qh, g_qh);     cudaGetSymbolAddress((void**)&ql, g_ql);
    cudaGetSymbolAddress((void**)&ath, g_ath);   cudaGetSymbolAddress((void**)&atl, g_atl);
    cudaGetSymbolAddress((void**)&x1f, g_x1f);
    cudaGetSymbolAddress((void**)&x1h, g_x1h);   cudaGetSymbolAddress((void**)&x1l, g_x1l);
    cudaGetSymbolAddress((void**)&hh, g_hh);     cudaGetSymbolAddress((void**)&hl, g_hl);
    cudaGetSymbolAddress((void**)&wqkvh, g_wqkvh); cudaGetSymbolAddress((void**)&wqkvl, g_wqkvl);
    cudaGetSymbolAddress((void**)&woh, g_woh);   cudaGetSymbolAddress((void**)&wol, g_wol);
    cudaGetSymbolAddress((void**)&w1h, g_w1h);   cudaGetSymbolAddress((void**)&w1l, g_w1l);
    cudaGetSymbolAddress((void**)&w2h, g_w2h);   cudaGetSymbolAddress((void**)&w2l, g_w2l);
    cudaGetSymbolAddress((void**)&bqkv, g_bqkv);

    cudaFuncSetAttribute(gemm_p<0>, cudaFuncAttributeMaxDynamicSharedMemorySize, SMEM_G);
    cudaFuncSetAttribute(gemm_p<1>, cudaFuncAttributeMaxDynamicSharedMemorySize, SMEM_G);
    cudaFuncSetAttribute(gemm_p<2>, cudaFuncAttributeMaxDynamicSharedMemorySize, SMEM_G);
    cudaFuncSetAttribute(gemm_p<3>, cudaFuncAttributeMaxDynamicSharedMemorySize, SMEM_G);
    cudaFuncSetAttribute(attn_kernel, cudaFuncAttributeMaxDynamicSharedMemorySize, SMEM_ATTN);

    // 0: merged prep
    prep_all<<<15366, 256>>>(x, bq, bk, bv, wq, wk, wv, wo, w1, w2);
    // 1: fused QKV projection -> planes   (N=1536/128 x M=49152/256)
    gemm_p<0><<<dim3(12, 192), 256, SMEM_G>>>(xh, xl, wqkvh, wqkvl, bqkv, nullptr,
                                              nullptr, qh, ql, NQKV, Ee);
    // 2: attention -> planes
    attn_kernel<<<Bb * Hh, 256, SMEM_ATTN>>>(qh, ql, ath, atl);
    // 3: x1 = x + attn @ wo + bo  (f32 + planes)
    gemm_p<1><<<dim3(4, 192), 256, SMEM_G>>>(ath, atl, woh, wol, bo, x,
                                             x1f, x1h, x1l, Ee, Ee);
    // 4: h = relu(x1 @ w1 + b1)   (planes)
    gemm_p<2><<<dim3(16, 192), 256, SMEM_G>>>(x1h, x1l, w1h, w1l, b1, nullptr,
                                              nullptr, hh, hl, Ff, Ee);
    // 5: out = x1 + h @ w2 + b2   (f32 final)
    gemm_p<3><<<dim3(4, 192), 256, SMEM_G>>>(hh, hl, w2h, w2l, b2, x1f,
                                             out, nullptr, nullptr, Ee, Ff);
}

// round 10
// speedup vs baseline: 1.3811x; 1.3705x over previous
#include <cuda_runtime.h>
#include <cstdint>

// ---------------------------------------------------------------------------
// Transformer block. QKV + attention + wo on bf16x3 HMMA (score path);
// MLP GEMMs on int8 2-limb IMMA m16n8k32 (exact s32 accum, 15-bit scales).
// B=384, S=128, E=512, H=4, D=128, F=2048.
// ---------------------------------------------------------------------------

constexpr int Bb = 384, Ss = 128, Ee = 512, Ff = 2048;
constexpr int MM = Bb * Ss, NQKV = 3 * Ee;

__device__ uint16_t g_xh [(size_t)MM * Ee], g_xl [(size_t)MM * Ee];
__device__ uint16_t g_qh [(size_t)MM * NQKV], g_ql [(size_t)MM * NQKV];
__device__ uint16_t g_ath[(size_t)MM * Ee], g_atl[(size_t)MM * Ee];
__device__ float    g_x1f[(size_t)MM * Ee];
__device__ float    g_hf [(size_t)MM * Ff];
__device__ int8_t   g_x1qh[(size_t)MM * Ee], g_x1ql[(size_t)MM * Ee];
__device__ int8_t   g_hqh [(size_t)MM * Ff], g_hql [(size_t)MM * Ff];
__device__ float    g_sx1[MM], g_sh[MM];
__device__ int8_t   g_w1qh[(size_t)Ff * Ee], g_w1ql[(size_t)Ff * Ee];
__device__ int8_t   g_w2qh[(size_t)Ee * Ff], g_w2ql[(size_t)Ee * Ff];
__device__ float    g_sw1[Ff], g_sw2[Ee];
__device__ uint16_t g_wqkvh[(size_t)NQKV * Ee], g_wqkvl[(size_t)NQKV * Ee];
__device__ uint16_t g_woh[(size_t)Ee * Ee], g_wol[(size_t)Ee * Ee];
__device__ float    g_bqkv[NQKV];

__device__ __forceinline__ void split2(float v, uint16_t& h, uint16_t& l) {
    float hf;
    asm("cvt.rn.bf16.f32 %0, %1;" : "=h"(h) : "f"(v));
    asm("cvt.f32.bf16 %0, %1;"    : "=f"(hf) : "h"(h));
    asm("cvt.rn.bf16.f32 %0, %1;" : "=h"(l) : "f"(v - hf));
}
__device__ __forceinline__ uint32_t cvta_s(const void* p) {
    uint32_t a;
    asm("{\n\t.reg .u64 t;\n\tcvta.to.shared.u64 t, %1;\n\tcvt.u32.u64 %0, t;\n\t}"
        : "=r"(a) : "l"(p));
    return a;
}
#define CP16(s, g)  asm volatile("cp.async.cg.shared.global [%0], [%1], 16;" ::"r"(s), "l"(g))
#define CPCOMMIT()  asm volatile("cp.async.commit_group;" ::: "memory")
__device__ __forceinline__ void cpwait(int n) {
    if (n >= 2)      asm volatile("cp.async.wait_group 2;" ::: "memory");
    else if (n == 1) asm volatile("cp.async.wait_group 1;" ::: "memory");
    else             asm volatile("cp.async.wait_group 0;" ::: "memory");
}
#define LDSM4(r0, r1, r2, r3, a) \
    asm volatile("ldmatrix.sync.aligned.m8n8.x4.shared.b16 {%0,%1,%2,%3}, [%4];" \
        : "=r"(r0), "=r"(r1), "=r"(r2), "=r"(r3) : "r"(a))
#define LDSM4T(r0, r1, r2, r3, a) \
    asm volatile("ldmatrix.sync.aligned.m8n8.x4.trans.shared.b16 {%0,%1,%2,%3}, [%4];" \
        : "=r"(r0), "=r"(r1), "=r"(r2), "=r"(r3) : "r"(a))
#define STS32(a, v) asm volatile("st.shared.b32 [%0], %1;" ::"r"(a), "r"(v) : "memory")

__device__ __forceinline__ void mma16(float* d, const uint32_t* a,
                                      uint32_t b0, uint32_t b1) {
    asm("mma.sync.aligned.m16n8k16.row.col.f32.bf16.bf16.f32 "
        "{%0,%1,%2,%3}, {%4,%5,%6,%7}, {%8,%9}, {%0,%1,%2,%3};\n"
        : "+f"(d[0]), "+f"(d[1]), "+f"(d[2]), "+f"(d[3])
        : "r"(a[0]), "r"(a[1]), "r"(a[2]), "r"(a[3]), "r"(b0), "r"(b1));
}
__device__ __forceinline__ void mma3(float* d, const uint32_t* ah, const uint32_t* al,
                                     uint32_t bh0, uint32_t bh1,
                                     uint32_t bl0, uint32_t bl1) {
    mma16(d, ah, bh0, bh1);
    mma16(d, al, bh0, bh1);
    mma16(d, ah, bl0, bl1);
}
__device__ __forceinline__ void imma32(int* d, const uint32_t* a,
                                       uint32_t b0, uint32_t b1) {
    asm("mma.sync.aligned.m16n8k32.row.col.s32.s8.s8.s32 "
        "{%0,%1,%2,%3}, {%4,%5,%6,%7}, {%8,%9}, {%0,%1,%2,%3};\n"
        : "+r"(d[0]), "+r"(d[1]), "+r"(d[2]), "+r"(d[3])
        : "r"(a[0]), "r"(a[1]), "r"(a[2]), "r"(a[3]), "r"(b0), "r"(b1));
}

// ---------------------------------------------------------------------------
// prep: x split | bias | wqkv+wo bf16 transpose | w1/w2 int8 limbs (col scale)
// blocks: [0,12288) x | [12288,12294) bias | [12294,13318) bf16 w |
//         [13318,13382) w1 q | [13382,13398) w2 q
// ---------------------------------------------------------------------------
__global__ void prep_all(const float* __restrict__ x,
                         const float* __restrict__ bq, const float* __restrict__ bk,
                         const float* __restrict__ bv,
                         const float* __restrict__ wq, const float* __restrict__ wk,
                         const float* __restrict__ wv, const float* __restrict__ wo,
                         const float* __restrict__ w1, const float* __restrict__ w2) {
    __shared__ uint32_t tile[32][33];
    __shared__ float smax[8][32];
    const int bidx = blockIdx.x;
    const int lx = threadIdx.x & 31, ly = threadIdx.x >> 5;
    if (bidx < 12288) {
        const size_t base = ((size_t)bidx * 256 + threadIdx.x) * 8;
        const float4 v0 = *(const float4*)(x + base);
        const float4 v1 = *(const float4*)(x + base + 4);
        uint16_t h[8], l[8];
        split2(v0.x, h[0], l[0]); split2(v0.y, h[1], l[1]);
        split2(v0.z, h[2], l[2]); split2(v0.w, h[3], l[3]);
        split2(v1.x, h[4], l[4]); split2(v1.y, h[5], l[5]);
        split2(v1.z, h[6], l[6]); split2(v1.w, h[7], l[7]);
        uint4 oh, ol;
        oh.x = h[0] | (h[1] << 16); oh.y = h[2] | (h[3] << 16);
        oh.z = h[4] | (h[5] << 16); oh.w = h[6] | (h[7] << 16);
        ol.x = l[0] | (l[1] << 16); ol.y = l[2] | (l[3] << 16);
        ol.z = l[4] | (l[5] << 16); ol.w = l[6] | (l[7] << 16);
        *(uint4*)(g_xh + base) = oh;
        *(uint4*)(g_xl + base) = ol;
        return;
    }
    if (bidx < 12294) {
        const int i = (bidx - 12288) * 256 + threadIdx.x;
        if (i < NQKV)
            g_bqkv[i] = i < 512 ? bq[i] : (i < 1024 ? bk[i - 512] : bv[i - 1024]);
        return;
    }
    const int id = bidx - 12294;
    if (id < 1024) {                       // bf16 transpose+split (wqkv, wo)
        const float* W; uint16_t *Dh, *Dl;
        int Nsrc, tx, ty, rowoff = 0;
        if (id < 768) {
            const int w = id >> 8, loc = id & 255;
            tx = loc & 15; ty = loc >> 4;
            W = w == 0 ? wq : (w == 1 ? wk : wv);
            Dh = g_wqkvh; Dl = g_wqkvl; Nsrc = 512; rowoff = w * 512;
        } else {
            const int loc = id - 768; tx = loc & 15; ty = loc >> 4;
            W = wo; Dh = g_woh; Dl = g_wol; Nsrc = 512;
        }
        const int kb = ty * 32, nb = tx * 32;
        for (int j = ly; j < 32; j += 8) {
            uint16_t h, l;
            split2(W[(size_t)(kb + j) * Nsrc + nb + lx], h, l);
            tile[j][lx] = (uint32_t)h | ((uint32_t)l << 16);
        }
        __syncthreads();
        for (int j = ly; j < 32; j += 8) {
            const uint32_t u = tile[lx][j];
            const size_t o = (size_t)(rowoff + nb + j) * 512 + kb + lx;
            Dh[o] = (uint16_t)u;
            Dl[o] = (uint16_t)(u >> 16);
        }
        return;
    }
    // int8 weight quant: per-out-col scale over full K, limbs q = 256h + l
    const float* W; int8_t *Qh, *Ql; float* Sd;
    int Nsrc, K, wb;
    if (id < 1088) { wb = id - 1024; W = w1; Qh = g_w1qh; Ql = g_w1ql; Sd = g_sw1; Nsrc = 2048; K = 512; }
    else           { wb = id - 1088; W = w2; Qh = g_w2qh; Ql = g_w2ql; Sd = g_sw2; Nsrc = 512;  K = 2048; }
    const int nb = wb * 32;
    float mx = 0.f;
    for (int k = ly; k < K; k += 8)
        mx = fmaxf(mx, fabsf(W[(size_t)k * Nsrc + nb + lx]));
    smax[ly][lx] = mx;
    __syncthreads();
    if (ly == 0) {
        for (int i = 1; i < 8; i++) mx = fmaxf(mx, smax[i][lx]);
        const float d = mx > 0.f ? mx * (1.f / 32639.f) : 1.f;
        smax[0][lx] = 1.f / d;
        Sd[nb + lx] = d;
    }
    __syncthreads();
    const float inv = smax[0][lx];
    for (int kb = 0; kb < K; kb += 32) {
        for (int j = ly; j < 32; j += 8) {
            const int q = (int)rintf(W[(size_t)(kb + j) * Nsrc + nb + lx] * inv);
            const int h = (q + 128) >> 8, l = q - (h << 8);
            tile[j][lx] = (uint32_t)(uint8_t)h | ((uint32_t)(uint8_t)l << 8);
        }
        __syncthreads();
        for (int j = ly; j < 32; j += 8) {
            const uint32_t t = tile[lx][j];
            const size_t o = (size_t)(nb + j) * K + kb + lx;
            Qh[o] = (int8_t)(t & 255);
            Ql[o] = (int8_t)((t >> 8) & 255);
        }
        __syncthreads();
    }
}

// ---------------------------------------------------------------------------
// quant_rows: f32 [M][KQ] -> s8 limb planes + per-row scale (1 warp / row)
// ---------------------------------------------------------------------------
template <int KQ>
__global__ __launch_bounds__(256)
void quant_rows(const float* __restrict__ src, int8_t* __restrict__ qh,
                int8_t* __restrict__ ql, float* __restrict__ sc) {
    const int w = threadIdx.x >> 5, lane = threadIdx.x & 31;
    const int row = blockIdx.x * 8 + w;
    const float* s = src + (size_t)row * KQ;
    constexpr int J = KQ / 128;
    float4 v[J];
    float mx = 0.f;
#pragma unroll
    for (int j = 0; j < J; j++) {
        v[j] = *(const float4*)(s + j * 128 + lane * 4);
        mx = fmaxf(mx, fmaxf(fmaxf(fabsf(v[j].x), fabsf(v[j].y)),
                             fmaxf(fabsf(v[j].z), fabsf(v[j].w))));
    }
#pragma unroll
    for (int o = 16; o; o >>= 1) mx = fmaxf(mx, __shfl_xor_sync(0xffffffffu, mx, o));
    const float d = mx > 0.f ? mx * (1.f / 32639.f) : 1.f;
    const float inv = 1.f / d;
    if (lane == 0) sc[row] = d;
#pragma unroll
    for (int j = 0; j < J; j++) {
        const int q0 = (int)rintf(v[j].x * inv), q1 = (int)rintf(v[j].y * inv);
        const int q2 = (int)rintf(v[j].z * inv), q3 = (int)rintf(v[j].w * inv);
        const int h0 = (q0 + 128) >> 8, h1 = (q1 + 128) >> 8;
        const int h2 = (q2 + 128) >> 8, h3 = (q3 + 128) >> 8;
        const int l0 = q0 - (h0 << 8), l1 = q1 - (h1 << 8);
        const int l2 = q2 - (h2 << 8), l3 = q3 - (h3 << 8);
        *(uint32_t*)(qh + (size_t)row * KQ + j * 128 + lane * 4) =
            (h0 & 255) | ((h1 & 255) << 8) | ((h2 & 255) << 16) | ((h3 & 255) << 24);
        *(uint32_t*)(ql + (size_t)row * KQ + j * 128 + lane * 4) =
            (l0 & 255) | ((l1 & 255) << 8) | ((l2 & 255) << 16) | ((l3 & 255) << 24);
    }
}

// ---------------------------------------------------------------------------
// int8 2-limb GEMM: out = epi((A@B^T)*sa*sb + bias [,res]). Tile 128x128,
// BK=128, 3-stage, 8 warps 2x4 (warp 64x32). EPI: 0 relu->f32; 1 +res->f32.
// ---------------------------------------------------------------------------
constexpr int I8_STGB = 65536;
constexpr int SMEM_I8 = 3 * I8_STGB;

template <int EPI>
__global__ __launch_bounds__(256, 1)
void gemm_i8(const int8_t* __restrict__ Ah_, const int8_t* __restrict__ Al_,
             const int8_t* __restrict__ Bh_, const int8_t* __restrict__ Bl_,
             const float* __restrict__ sa, const float* __restrict__ sb,
             const float* __restrict__ bias, const float* __restrict__ res,
             float* __restrict__ out, int Nout, int K) {
    extern __shared__ char smraw[];
    const uint32_t sbase = cvta_s(smraw);
    const int tid = threadIdx.x, wid = tid >> 5, lane = tid & 31;
    const int wm = wid >> 2, wn = wid & 3;
    const int mB = blockIdx.y * 128, nB = blockIdx.x * 128;
    const int l7 = lane & 7, l8 = (lane >> 3) & 1, l16 = lane >> 4;

    const int trow = tid >> 3, tch = tid & 7;
    const uint32_t dst0 = trow * 128 + (((uint32_t)tch ^ (trow & 7)) << 4);
    const int8_t* bp[4];
    bp[0] = Ah_ + (size_t)(mB + trow) * K + tch * 16;
    bp[1] = Al_ + (size_t)(mB + trow) * K + tch * 16;
    bp[2] = Bh_ + (size_t)(nB + trow) * K + tch * 16;
    bp[3] = Bl_ + (size_t)(nB + trow) * K + tch * 16;

    int hh[4][4][4], cr[4][4][4];
#pragma unroll
    for (int a = 0; a < 4; a++)
#pragma unroll
        for (int b = 0; b < 4; b++)
#pragma unroll
            for (int c = 0; c < 4; c++) { hh[a][b][c] = 0; cr[a][b][c] = 0; }

    auto issue = [&](int s) {
        const uint32_t stb = sbase + (s % 3) * I8_STGB;
        const int kg = s * 128;
#pragma unroll
        for (int pl = 0; pl < 4; pl++) {
            const int8_t* gp = bp[pl] + kg;
#pragma unroll
            for (int i2 = 0; i2 < 4; i2++)
                CP16(stb + pl * 16384 + dst0 + i2 * 4096, gp + (size_t)i2 * 32 * K);
        }
        CPCOMMIT();
    };

    const int nT = K >> 7;
    issue(0);
    if (nT > 1) issue(1);

    const uint32_t raBase[4] = {
        (uint32_t)(wm * 64 + 0 + l8 * 8 + l7),  (uint32_t)(wm * 64 + 16 + l8 * 8 + l7),
        (uint32_t)(wm * 64 + 32 + l8 * 8 + l7), (uint32_t)(wm * 64 + 48 + l8 * 8 + l7)};
    const uint32_t rbBase[2] = {
        (uint32_t)(wn * 32 + l8 * 8 + l7), (uint32_t)(wn * 32 + 16 + l8 * 8 + l7)};

    for (int t = 0; t < nT; t++) {
        cpwait(t < nT - 1 ? 1 : 0);
        __syncthreads();
        if (t + 2 < nT) issue(t + 2);
        const uint32_t stb = sbase + (t % 3) * I8_STGB;
#pragma unroll
        for (int b = 0; b < 4; b++) {
            uint32_t ahf[4][4], alf[4][4];
#pragma unroll
            for (int mi = 0; mi < 4; mi++) {
                const uint32_t r = raBase[mi];
                const uint32_t base = stb + r * 128;
                const uint32_t ch = (uint32_t)((2 * b + l16) ^ (r & 7)) << 4;
                LDSM4(ahf[mi][0], ahf[mi][1], ahf[mi][2], ahf[mi][3], base + ch);
                LDSM4(alf[mi][0], alf[mi][1], alf[mi][2], alf[mi][3], base + 16384 + ch);
            }
#pragma unroll
            for (int j2 = 0; j2 < 2; j2++) {
                const uint32_t r = rbBase[j2];
                const uint32_t baseB = stb + 32768 + r * 128;
                const uint32_t ch = (uint32_t)((2 * b + l16) ^ (r & 7)) << 4;
                uint32_t bh0, bh1, bh2, bh3, bl0, bl1, bl2, bl3;
                LDSM4(bh0, bh1, bh2, bh3, baseB + ch);
                LDSM4(bl0, bl1, bl2, bl3, baseB + 16384 + ch);
#pragma unroll
                for (int mi = 0; mi < 4; mi++) {
                    imma32(hh[mi][2 * j2],     ahf[mi], bh0, bh2);
                    imma32(hh[mi][2 * j2 + 1], ahf[mi], bh1, bh3);
                }
#pragma unroll
                for (int mi = 0; mi < 4; mi++) {
                    imma32(cr[mi][2 * j2],     ahf[mi], bl0, bl2);
                    imma32(cr[mi][2 * j2 + 1], ahf[mi], bl1, bl3);
                }
#pragma unroll
                for (int mi = 0; mi < 4; mi++) {
                    imma32(cr[mi][2 * j2],     alf[mi], bh0, bh2);
                    imma32(cr[mi][2 * j2 + 1], alf[mi], bh1, bh3);
                }
            }
        }
    }

#pragma unroll
    for (int mi = 0; mi < 4; mi++) {
        const int r0 = mB + wm * 64 + mi * 16 + (lane >> 2);
        const int r1 = r0 + 8;
        const float sa0 = sa[r0], sa1 = sa[r1];
#pragma unroll
        for (int nj = 0; nj < 4; nj++) {
            const int c = nB + wn * 32 + nj * 8 + 2 * (lane & 3);
            const float sb0 = sb[c], sb1 = sb[c + 1];
            const float b0 = bias[c], b1v = bias[c + 1];
            float v0 = ((float)hh[mi][nj][0] * 65536.f + (float)cr[mi][nj][0] * 256.f) * (sa0 * sb0) + b0;
            float v1 = ((float)hh[mi][nj][1] * 65536.f + (float)cr[mi][nj][1] * 256.f) * (sa0 * sb1) + b1v;
            float v2 = ((float)hh[mi][nj][2] * 65536.f + (float)cr[mi][nj][2] * 256.f) * (sa1 * sb0) + b0;
            float v3 = ((float)hh[mi][nj][3] * 65536.f + (float)cr[mi][nj][3] * 256.f) * (sa1 * sb1) + b1v;
            if (EPI == 0) {
                v0 = fmaxf(v0, 0.f); v1 = fmaxf(v1, 0.f);
                v2 = fmaxf(v2, 0.f); v3 = fmaxf(v3, 0.f);
            } else {
                const float2 rv0 = *(const float2*)(res + (size_t)r0 * Nout + c);
                const float2 rv1 = *(const float2*)(res + (size_t)r1 * Nout + c);
                v0 += rv0.x; v1 += rv0.y; v2 += rv1.x; v3 += rv1.y;
            }
            *(float2*)(out + (size_t)r0 * Nout + c) = make_float2(v0, v1);
            *(float2*)(out + (size_t)r1 * Nout + c) = make_float2(v2, v3);
        }
    }
}

// ---------------------------------------------------------------------------
// bf16x3 GEMM (QKV, wo). EPI: 0 = +bias -> planes; 3 = +bias+res -> f32.
// 256 thr, tile 256x128, BK=32, 4 stages, term-major passes (as R8).
// ---------------------------------------------------------------------------
constexpr int ST = 4, A_BYTES = 256 * 128, B_OFF = A_BYTES;
constexpr int STGB = A_BYTES + 128 * 128, SMEM_G = ST * STGB;

template <int EPI>
__global__ __launch_bounds__(256, 1)
void gemm_p(const uint16_t* __restrict__ Ah_, const uint16_t* __restrict__ Al_,
            const uint16_t* __restrict__ Bh_, const uint16_t* __restrict__ Bl_,
            const float* __restrict__ bias, const float* __restrict__ res,
            float* __restrict__ Cf,
            uint16_t* __restrict__ Ch, uint16_t* __restrict__ Cl,
            int Nout, int K) {
    extern __shared__ char smraw[];
    const uint32_t sb = cvta_s(smraw);
    const int tid = threadIdx.x, wid = tid >> 5, lane = tid & 31;
    const int wm = wid >> 1, wn = wid & 1;
    const int mB = blockIdx.y * 256, nB = blockIdx.x * 128;
    const int l7 = lane & 7, l8 = (lane >> 3) & 1, l16 = lane >> 4;

    const int trow = tid >> 3, tch = tid & 7;
    const int kofs = (tch & 3) * 8;
    const uint32_t dA0 = trow * 128 + (((uint32_t)tch ^ (trow & 7)) << 4);
    const uint32_t dB0 = B_OFF + dA0;
    const uint16_t* gA = (tch < 4 ? Ah_ : Al_) + (size_t)(mB + trow) * K + kofs;
    const uint16_t* gB = (tch < 4 ? Bh_ : Bl_) + (size_t)(nB + trow) * K + kofs;
    const size_t aStep = (size_t)32 * K;

    float acc[4][8][4];
#pragma unroll
    for (int a = 0; a < 4; a++)
#pragma unroll
        for (int b = 0; b < 8; b++)
#pragma unroll
            for (int c = 0; c < 4; c++) acc[a][b][c] = 0.f;

    auto issue = [&](int s) {
        const uint32_t stb = sb + (s & (ST - 1)) * STGB;
        const uint16_t* ga = gA + (size_t)s * 32;
        const uint16_t* gb = gB + (size_t)s * 32;
#pragma unroll
        for (int i = 0; i < 8; i++) CP16(stb + dA0 + i * 4096, ga + (size_t)i * aStep);
#pragma unroll
        for (int i = 0; i < 4; i++) CP16(stb + dB0 + i * 4096, gb + (size_t)i * aStep);
        CPCOMMIT();
    };

    const int nT = K >> 5;
    for (int s = 0; s < ST - 1 && s < nT; s++) issue(s);

    const uint32_t raBase[4] = {
        (uint32_t)(wm * 64 + 0 + l8 * 8 + l7),  (uint32_t)(wm * 64 + 16 + l8 * 8 + l7),
        (uint32_t)(wm * 64 + 32 + l8 * 8 + l7), (uint32_t)(wm * 64 + 48 + l8 * 8 + l7)};
    const uint32_t rbBase[4] = {
        (uint32_t)(wn * 64 + 0 + l8 * 8 + l7),  (uint32_t)(wn * 64 + 16 + l8 * 8 + l7),
        (uint32_t)(wn * 64 + 32 + l8 * 8 + l7), (uint32_t)(wn * 64 + 48 + l8 * 8 + l7)};

    for (int t = 0; t < nT; t++) {
        const int rem = nT - 1 - t;
        cpwait(rem < 2 ? rem : 2);
        __syncthreads();
        if (t + ST - 1 < nT) issue(t + ST - 1);
        const uint32_t stb = sb + (t & (ST - 1)) * STGB;
#pragma unroll
        for (int h = 0; h < 2; h++) {
            uint32_t ah[4][4], al[4][4], bhm[4][4], blm[4][4];
#pragma unroll
            for (int mi = 0; mi < 4; mi++) {
                const uint32_t r = raBase[mi];
                const uint32_t base = stb + r * 128;
                const uint32_t ch = (uint32_t)(2 * h + l16) ^ (r & 7);
                const uint32_t cl = (uint32_t)(4 + 2 * h + l16) ^ (r & 7);
                LDSM4(ah[mi][0], ah[mi][1], ah[mi][2], ah[mi][3], base + (ch << 4));
                LDSM4(al[mi][0], al[mi][1], al[mi][2], al[mi][3], base + (cl << 4));
            }
#pragma unroll
            for (int j2 = 0; j2 < 4; j2++) {
                const uint32_t r = rbBase[j2];
                const uint32_t base = stb + B_OFF + r * 128;
                const uint32_t ch = (uint32_t)(2 * h + l16) ^ (r & 7);
                const uint32_t cl = (uint32_t)(4 + 2 * h + l16) ^ (r & 7);
                LDSM4(bhm[j2][0], bhm[j2][1], bhm[j2][2], bhm[j2][3], base + (ch << 4));
                LDSM4(blm[j2][0], blm[j2][1], blm[j2][2], blm[j2][3], base + (cl << 4));
            }
#pragma unroll
            for (int j2 = 0; j2 < 4; j2++)
#pragma unroll
                for (int mi = 0; mi < 4; mi++)
#pragma unroll
                    for (int jj = 0; jj < 2; jj++)
                        mma16(acc[mi][2 * j2 + jj], ah[mi], bhm[j2][jj], bhm[j2][2 + jj]);
#pragma unroll
            for (int j2 = 0; j2 < 4; j2++)
#pragma unroll
                for (int mi = 0; mi < 4; mi++)
#pragma unroll
                    for (int jj = 0; jj < 2; jj++)
                        mma16(acc[mi][2 * j2 + jj], al[mi], bhm[j2][jj], bhm[j2][2 + jj]);
#pragma unroll
            for (int j2 = 0; j2 < 4; j2++)
#pragma unroll
                for (int mi = 0; mi < 4; mi++)
#pragma unroll
                    for (int jj = 0; jj < 2; jj++)
                        mma16(acc[mi][2 * j2 + jj], ah[mi], blm[j2][jj], blm[j2][2 + jj]);
        }
    }

#pragma unroll
    for (int mi = 0; mi < 4; mi++) {
        const int r0 = mB + wm * 64 + mi * 16 + (lane >> 2);
#pragma unroll
        for (int nj = 0; nj < 8; nj++) {
            const int c = nB + wn * 64 + nj * 8 + 2 * (lane & 3);
#pragma unroll
            for (int half = 0; half < 2; half++) {
                const int r = r0 + half * 8;
                float v0 = acc[mi][nj][2 * half] + bias[c];
                float v1 = acc[mi][nj][2 * half + 1] + bias[c + 1];
                if (EPI == 3) {
                    const float2 rv = *(const float2*)(res + (size_t)r * Nout + c);
                    v0 += rv.x; v1 += rv.y;
                    *(float2*)(Cf + (size_t)r * Nout + c) = make_float2(v0, v1);
                } else {
                    uint16_t h0, l0, h1, l1;
                    split2(v0, h0, l0); split2(v1, h1, l1);
                    *(uint32_t*)(Ch + (size_t)r * Nout + c) = (uint32_t)h0 | ((uint32_t)h1 << 16);
                    *(uint32_t*)(Cl + (size_t)r * Nout + c) = (uint32_t)l0 | ((uint32_t)l1 << 16);
                }
            }
        }
    }
}

// ---------------------------------------------------------------------------
// Attention on bf16 planes (unchanged from R8).
// ---------------------------------------------------------------------------
constexpr int SMEM_ATTN = 6 * 32768;

__global__ __launch_bounds__(256, 1)
void attn_kernel(const uint16_t* __restrict__ qh, const uint16_t* __restrict__ ql,
                 uint16_t* __restrict__ Oh, uint16_t* __restrict__ Ol) {
    extern __shared__ char smraw[];
    const uint32_t sb = cvta_s(smraw);
    const uint32_t QH = sb, QL = sb + 32768, KH = sb + 65536, KL = sb + 98304;
    const uint32_t VH = sb + 131072, VL = sb + 163840;

    const int tid = threadIdx.x, bh = blockIdx.x;
    const int bb = bh >> 2, head = bh & 3;
    const size_t rowbase = (size_t)bb * Ss * NQKV;
    const int coloff = head * 128;
    const size_t obase = (size_t)bb * Ss * Ee + (size_t)coloff;

#pragma unroll
    for (int i = 0; i < 48; i++) {
        const int idx = tid + i * 256;
        const int p = idx >> 11, rem = idx & 2047;
        const int row = rem >> 4, c = rem & 15;
        const uint16_t* base = (p & 1) ? ql : qh;
        const size_t src = rowbase + (size_t)row * NQKV + (p >> 1) * 512 + coloff + c * 8;
        CP16(sb + p * 32768 + row * 256 + ((uint32_t)(c ^ (row & 7)) << 4), base + src);
    }
    CPCOMMIT();
    cpwait(0);
    __syncthreads();

    const int wid = tid >> 5, lane = tid & 31;
    const int g = lane >> 2, q = lane & 3;
    const int l7 = lane & 7, l8 = (lane >> 3) & 1, l16 = lane >> 4;
    const int rbase = wid * 16;
    const int ra = rbase + l8 * 8 + l7;

    float acc[16][4];
#pragma unroll
    for (int j = 0; j < 16; j++)
#pragma unroll
        for (int c = 0; c < 4; c++) acc[j][c] = 0.f;

#pragma unroll
    for (int kk = 0; kk < 8; kk++) {
        const uint32_t ca = ((uint32_t)((2 * kk + l16) ^ (ra & 7)) << 4) + ra * 256;
        uint32_t ah[4], al[4];
        LDSM4(ah[0], ah[1], ah[2], ah[3], QH + ca);
        LDSM4(al[0], al[1], al[2], al[3], QL + ca);
#pragma unroll
        for (int j2 = 0; j2 < 8; j2++) {
            const int rb = j2 * 16 + l8 * 8 + l7;
            const uint32_t cb = ((uint32_t)((2 * kk + l16) ^ (rb & 7)) << 4) + rb * 256;
            uint32_t bh_[4], bl_[4];
            LDSM4(bh_[0], bh_[1], bh_[2], bh_[3], KH + cb);
            LDSM4(bl_[0], bl_[1], bl_[2], bl_[3], KL + cb);
            mma3(acc[j2 * 2],     ah, al, bh_[0], bh_[2], bl_[0], bl_[2]);
            mma3(acc[j2 * 2 + 1], ah, al, bh_[1], bh_[3], bl_[1], bl_[3]);
        }
    }

    float m0 = -1e30f, m1 = -1e30f;
#pragma unroll
    for (int j = 0; j < 16; j++) {
        m0 = fmaxf(m0, fmaxf(acc[j][0], acc[j][1]));
        m1 = fmaxf(m1, fmaxf(acc[j][2], acc[j][3]));
    }
    m0 = fmaxf(m0, __shfl_xor_sync(0xffffffffu, m0, 1));
    m0 = fmaxf(m0, __shfl_xor_sync(0xffffffffu, m0, 2));
    m1 = fmaxf(m1, __shfl_xor_sync(0xffffffffu, m1, 1));
    m1 = fmaxf(m1, __shfl_xor_sync(0xffffffffu, m1, 2));
    float s0 = 0.f, s1 = 0.f;
#pragma unroll
    for (int j = 0; j < 16; j++) {
        acc[j][0] = expf(acc[j][0] - m0);
        acc[j][1] = expf(acc[j][1] - m0);
        acc[j][2] = expf(acc[j][2] - m1);
        acc[j][3] = expf(acc[j][3] - m1);
        s0 += acc[j][0] + acc[j][1];
        s1 += acc[j][2] + acc[j][3];
    }
    s0 += __shfl_xor_sync(0xffffffffu, s0, 1);
    s0 += __shfl_xor_sync(0xffffffffu, s0, 2);
    s1 += __shfl_xor_sync(0xffffffffu, s1, 1);
    s1 += __shfl_xor_sync(0xffffffffu, s1, 2);
    const float r0s = 1.f / s0, r1s = 1.f / s1;

    const int pr0 = rbase + g, pr1 = pr0 + 8;
#pragma unroll
    for (int j = 0; j < 16; j++) {
        const uint32_t off0 = pr0 * 256 + ((uint32_t)(j ^ (pr0 & 7)) << 4) + 4 * q;
        const uint32_t off1 = pr1 * 256 + ((uint32_t)(j ^ (pr1 & 7)) << 4) + 4 * q;
        uint16_t h0, l0, h1, l1;
        split2(acc[j][0] * r0s, h0, l0); split2(acc[j][1] * r0s, h1, l1);
        STS32(QH + off0, (uint32_t)h0 | ((uint32_t)h1 << 16));
        STS32(QL + off0, (uint32_t)l0 | ((uint32_t)l1 << 16));
        split2(acc[j][2] * r1s, h0, l0); split2(acc[j][3] * r1s, h1, l1);
        STS32(QH + off1, (uint32_t)h0 | ((uint32_t)h1 << 16));
        STS32(QL + off1, (uint32_t)l0 | ((uint32_t)l1 << 16));
    }
    __syncwarp();

    float acc2[16][4];
#pragma unroll
    for (int j = 0; j < 16; j++)
#pragma unroll
        for (int c = 0; c < 4; c++) acc2[j][c] = 0.f;

#pragma unroll
    for (int kk = 0; kk < 8; kk++) {
        const uint32_t ca = ((uint32_t)((2 * kk + l16) ^ (ra & 7)) << 4) + ra * 256;
        uint32_t ah[4], al[4];
        LDSM4(ah[0], ah[1], ah[2], ah[3], QH + ca);
        LDSM4(al[0], al[1], al[2], al[3], QL + ca);
        const int krow = kk * 16 + l8 * 8 + l7;
#pragma unroll
        for (int j2 = 0; j2 < 8; j2++) {
            const int cj = j2 * 2 + l16;
            const uint32_t cb = ((uint32_t)(cj ^ (krow & 7)) << 4) + krow * 256;
            uint32_t vh_[4], vl_[4];
            LDSM4T(vh_[0], vh_[1], vh_[2], vh_[3], VH + cb);
            LDSM4T(vl_[0], vl_[1], vl_[2], vl_[3], VL + cb);
            mma3(acc2[j2 * 2],     ah, al, vh_[0], vh_[1], vl_[0], vl_[1]);
            mma3(acc2[j2 * 2 + 1], ah, al, vh_[2], vh_[3], vl_[2], vl_[3]);
        }
    }

#pragma unroll
    for (int j = 0; j < 16; j++) {
        const int c = j * 8 + 2 * q;
        const size_t o0 = obase + (size_t)(rbase + g) * Ee + c;
        const size_t o1 = o0 + (size_t)8 * Ee;
        uint16_t h0, l0, h1, l1;
        split2(acc2[j][0], h0, l0); split2(acc2[j][1], h1, l1);
        *(uint32_t*)(Oh + o0) = (uint32_t)h0 | ((uint32_t)h1 << 16);
        *(uint32_t*)(Ol + o0) = (uint32_t)l0 | ((uint32_t)l1 << 16);
        split2(acc2[j][2], h0, l0); split2(acc2[j][3], h1, l1);
        *(uint32_t*)(Oh + o1) = (uint32_t)h0 | ((uint32_t)h1 << 16);
        *(uint32_t*)(Ol + o1) = (uint32_t)l0 | ((uint32_t)l1 << 16);
    }
}

// ---------------------------------------------------------------------------
// launch
// ---------------------------------------------------------------------------
extern "C" void kernel_launch(void* const* d_in, const int* in_sizes, int n_in,
                              void* d_out, int out_size) {
    (void)in_sizes; (void)n_in; (void)out_size;
    const float* x  = (const float*)d_in[0];
    const float* wq = (const float*)d_in[1];
    const float* bq = (const float*)d_in[2];
    const float* wk = (const float*)d_in[3];
    const float* bk = (const float*)d_in[4];
    const float* wv = (const float*)d_in[5];
    const float* bv = (const float*)d_in[6];
    const float* wo = (const float*)d_in[7];
    const float* bo = (const float*)d_in[8];
    const float* w1 = (const float*)d_in[9];
    const float* b1 = (const float*)d_in[10];
    const float* w2 = (const float*)d_in[11];
    const float* b2 = (const float*)d_in[12];
    float* out = (float*)d_out;

    uint16_t *xh, *xl, *qh, *ql, *ath, *atl, *wqkvh, *wqkvl, *woh, *wol;
    int8_t *x1qh, *x1ql, *hqh, *hql, *w1qh, *w1ql, *w2qh, *w2ql;
    float *x1f, *hf, *sx1, *sh, *sw1, *sw2, *bqkv;
    cudaGetSymbolAddress((void**)&xh, g_xh);     cudaGetSymbolAddress((void**)&xl, g_xl);
    cudaGetSymbolAddress((void**)&qh, g_qh);     cudaGetSymbolAddress((void**)&ql, g_ql);
    cudaGetSymbolAddress((void**)&ath, g_ath);   cudaGetSymbolAddress((void**)&atl, g_atl);
    cudaGetSymbolAddress((void**)&x1f, g_x1f);   cudaGetSymbolAddress((void**)&hf, g_hf);
    cudaGetSymbolAddress((void**)&x1qh, g_x1qh); cudaGetSymbolAddress((void**)&x1ql, g_x1ql);
    cudaGetSymbolAddress((void**)&hqh, g_hqh);   cudaGetSymbolAddress((void**)&hql, g_hql);
    cudaGetSymbolAddress((void**)&sx1, g_sx1);   cudaGetSymbolAddress((void**)&sh, g_sh);
    cudaGetSymbolAddress((void**)&w1qh, g_w1qh); cudaGetSymbolAddress((void**)&w1ql, g_w1ql);
    cudaGetSymbolAddress((void**)&w2qh, g_w2qh); cudaGetSymbolAddress((void**)&w2ql, g_w2ql);
    cudaGetSymbolAddress((void**)&sw1, g_sw1);   cudaGetSymbolAddress((void**)&sw2, g_sw2);
    cudaGetSymbolAddress((void**)&wqkvh, g_wqkvh); cudaGetSymbolAddress((void**)&wqkvl, g_wqkvl);
    cudaGetSymbolAddress((void**)&woh, g_woh);   cudaGetSymbolAddress((void**)&wol, g_wol);
    cudaGetSymbolAddress((void**)&bqkv, g_bqkv);

    cudaFuncSetAttribute(gemm_p<0>, cudaFuncAttributeMaxDynamicSharedMemorySize, SMEM_G);
    cudaFuncSetAttribute(gemm_p<3>, cudaFuncAttributeMaxDynamicSharedMemorySize, SMEM_G);
    cudaFuncSetAttribute(gemm_i8<0>, cudaFuncAttributeMaxDynamicSharedMemorySize, SMEM_I8);
    cudaFuncSetAttribute(gemm_i8<1>, cudaFuncAttributeMaxDynamicSharedMemorySize, SMEM_I8);
    cudaFuncSetAttribute(attn_kernel, cudaFuncAttributeMaxDynamicSharedMemorySize, SMEM_ATTN);

    // 0: prep (x split + bias + bf16 weights + int8 w1/w2)
    prep_all<<<13398, 256>>>(x, bq, bk, bv, wq, wk, wv, wo, w1, w2);
    // 1: fused QKV -> planes
    gemm_p<0><<<dim3(12, 192), 256, SMEM_G>>>(xh, xl, wqkvh, wqkvl, bqkv, nullptr,
                                              nullptr, qh, ql, NQKV, Ee);
    // 2: attention -> planes
    attn_kernel<<<Bb * 4, 256, SMEM_ATTN>>>(qh, ql, ath, atl);
    // 3: x1 = x + attn @ wo + bo -> f32
    gemm_p<3><<<dim3(4, 192), 256, SMEM_G>>>(ath, atl, woh, wol, bo, x,
                                             x1f, nullptr, nullptr, Ee, Ee);
    // 4: quantize x1 rows
    quant_rows<Ee><<<MM / 8, 256>>>(x1f, x1qh, x1ql, sx1);
    // 5: h = relu(x1 @ w1 + b1) -> f32   <- ncu -s 5 captures int8 GEMM
    gemm_i8<0><<<dim3(16, 384), 256, SMEM_I8>>>(x1qh, x1ql, w1qh, w1ql, sx1, sw1,
                                                b1, nullptr, hf, Ff, Ee);
    // 6: quantize h rows
    quant_rows<Ff><<<MM / 8, 256>>>(hf, hqh, hql, sh);
    // 7: out = x1 + h @ w2 + b2 -> f32
    gemm_i8<1><<<dim3(4, 384), 256, SMEM_I8>>>(hqh, hql, w2qh, w2ql, sh, sw2,
                                               b2, x1f, out, Ee, Ff);
}

// round 11
// speedup vs baseline: 1.6935x; 1.2262x over previous
#include <cuda_runtime.h>
#include <cstdint>

// ---------------------------------------------------------------------------
// Transformer block — ALL GEMMs on int8 2-limb IMMA m16n8k32 (q = 256h + l,
// 15-bit, exact s32 accum of HH and HL+LH, per-row/per-col scales).
// Attention stays bf16x3 HMMA on planes produced by the QKV int8 epilogue.
// B=384, S=128, E=512, H=4, D=128, F=2048.
// ---------------------------------------------------------------------------

constexpr int Bb = 384, Ss = 128, Ee = 512, Ff = 2048;
constexpr int MM = Bb * Ss, NQKV = 3 * Ee;

// activations
__device__ int8_t   g_xqh [(size_t)MM * Ee],  g_xql [(size_t)MM * Ee];
__device__ float    g_sx[MM];
__device__ uint16_t g_qh [(size_t)MM * NQKV], g_ql [(size_t)MM * NQKV];
__device__ float    g_attf[(size_t)MM * Ee];
__device__ int8_t   g_atqh[(size_t)MM * Ee],  g_atql[(size_t)MM * Ee];
__device__ float    g_sat[MM];
__device__ float    g_x1f[(size_t)MM * Ee];
__device__ int8_t   g_x1qh[(size_t)MM * Ee],  g_x1ql[(size_t)MM * Ee];
__device__ float    g_sx1[MM];
__device__ float    g_hf [(size_t)MM * Ff];
__device__ int8_t   g_hqh [(size_t)MM * Ff],  g_hql [(size_t)MM * Ff];
__device__ float    g_sh[MM];
// weights (int8 limbs, [N][K], per-col scale)
__device__ int8_t   g_wqkvqh[(size_t)NQKV * Ee], g_wqkvql[(size_t)NQKV * Ee];
__device__ float    g_swqkv[NQKV];
__device__ int8_t   g_woqh[(size_t)Ee * Ee],  g_woql[(size_t)Ee * Ee];
__device__ float    g_swo[Ee];
__device__ int8_t   g_w1qh[(size_t)Ff * Ee],  g_w1ql[(size_t)Ff * Ee];
__device__ float    g_sw1[Ff];
__device__ int8_t   g_w2qh[(size_t)Ee * Ff],  g_w2ql[(size_t)Ee * Ff];
__device__ float    g_sw2[Ee];
__device__ float    g_bqkv[NQKV];

__device__ __forceinline__ void split2(float v, uint16_t& h, uint16_t& l) {
    float hf;
    asm("cvt.rn.bf16.f32 %0, %1;" : "=h"(h) : "f"(v));
    asm("cvt.f32.bf16 %0, %1;"    : "=f"(hf) : "h"(h));
    asm("cvt.rn.bf16.f32 %0, %1;" : "=h"(l) : "f"(v - hf));
}
__device__ __forceinline__ uint32_t cvta_s(const void* p) {
    uint32_t a;
    asm("{\n\t.reg .u64 t;\n\tcvta.to.shared.u64 t, %1;\n\tcvt.u32.u64 %0, t;\n\t}"
        : "=r"(a) : "l"(p));
    return a;
}
#define CP16(s, g)  asm volatile("cp.async.cg.shared.global [%0], [%1], 16;" ::"r"(s), "l"(g))
#define CPCOMMIT()  asm volatile("cp.async.commit_group;" ::: "memory")
__device__ __forceinline__ void cpwait(int n) {
    if (n >= 2)      asm volatile("cp.async.wait_group 2;" ::: "memory");
    else if (n == 1) asm volatile("cp.async.wait_group 1;" ::: "memory");
    else             asm volatile("cp.async.wait_group 0;" ::: "memory");
}
#define LDSM4(r0, r1, r2, r3, a) \
    asm volatile("ldmatrix.sync.aligned.m8n8.x4.shared.b16 {%0,%1,%2,%3}, [%4];" \
        : "=r"(r0), "=r"(r1), "=r"(r2), "=r"(r3) : "r"(a))
#define LDSM4T(r0, r1, r2, r3, a) \
    asm volatile("ldmatrix.sync.aligned.m8n8.x4.trans.shared.b16 {%0,%1,%2,%3}, [%4];" \
        : "=r"(r0), "=r"(r1), "=r"(r2), "=r"(r3) : "r"(a))
#define STS32(a, v) asm volatile("st.shared.b32 [%0], %1;" ::"r"(a), "r"(v) : "memory")

__device__ __forceinline__ void mma16(float* d, const uint32_t* a,
                                      uint32_t b0, uint32_t b1) {
    asm("mma.sync.aligned.m16n8k16.row.col.f32.bf16.bf16.f32 "
        "{%0,%1,%2,%3}, {%4,%5,%6,%7}, {%8,%9}, {%0,%1,%2,%3};\n"
        : "+f"(d[0]), "+f"(d[1]), "+f"(d[2]), "+f"(d[3])
        : "r"(a[0]), "r"(a[1]), "r"(a[2]), "r"(a[3]), "r"(b0), "r"(b1));
}
__device__ __forceinline__ void mma3(float* d, const uint32_t* ah, const uint32_t* al,
                                     uint32_t bh0, uint32_t bh1,
                                     uint32_t bl0, uint32_t bl1) {
    mma16(d, ah, bh0, bh1);
    mma16(d, al, bh0, bh1);
    mma16(d, ah, bl0, bl1);
}
__device__ __forceinline__ void imma32(int* d, const uint32_t* a,
                                       uint32_t b0, uint32_t b1) {
    asm("mma.sync.aligned.m16n8k32.row.col.s32.s8.s8.s32 "
        "{%0,%1,%2,%3}, {%4,%5,%6,%7}, {%8,%9}, {%0,%1,%2,%3};\n"
        : "+r"(d[0]), "+r"(d[1]), "+r"(d[2]), "+r"(d[3])
        : "r"(a[0]), "r"(a[1]), "r"(a[2]), "r"(a[3]), "r"(b0), "r"(b1));
}

// ---------------------------------------------------------------------------
// prep: bias concat (blocks 0..5) + int8 quant of all weights (blocks 6..149)
// per-out-col scale over full K, limbs q = 256h + l, transposed to [N][K].
// ---------------------------------------------------------------------------
__global__ void prep_all(const float* __restrict__ bq, const float* __restrict__ bk,
                         const float* __restrict__ bv,
                         const float* __restrict__ wq, const float* __restrict__ wk,
                         const float* __restrict__ wv, const float* __restrict__ wo,
                         const float* __restrict__ w1, const float* __restrict__ w2) {
    __shared__ uint32_t tile[32][33];
    __shared__ float smax[8][32];
    const int bidx = blockIdx.x;
    const int lx = threadIdx.x & 31, ly = threadIdx.x >> 5;
    if (bidx < 6) {
        const int i = bidx * 256 + threadIdx.x;
        if (i < NQKV)
            g_bqkv[i] = i < 512 ? bq[i] : (i < 1024 ? bk[i - 512] : bv[i - 1024]);
        return;
    }
    const int id = bidx - 6;
    const float* W; int8_t *Qh, *Ql; float* Sd;
    int Nsrc, K, nb, srccol, destrow;
    if (id < 48) {                       // wqkv
        nb = id * 32;
        W = nb < 512 ? wq : (nb < 1024 ? wk : wv);
        srccol = nb & 511; destrow = nb;
        Qh = g_wqkvqh; Ql = g_wqkvql; Sd = g_swqkv; Nsrc = 512; K = 512;
    } else if (id < 64) {                // wo
        nb = (id - 48) * 32; srccol = nb; destrow = nb;
        W = wo; Qh = g_woqh; Ql = g_woql; Sd = g_swo; Nsrc = 512; K = 512;
    } else if (id < 128) {               // w1
        nb = (id - 64) * 32; srccol = nb; destrow = nb;
        W = w1; Qh = g_w1qh; Ql = g_w1ql; Sd = g_sw1; Nsrc = 2048; K = 512;
    } else {                             // w2
        nb = (id - 128) * 32; srccol = nb; destrow = nb;
        W = w2; Qh = g_w2qh; Ql = g_w2ql; Sd = g_sw2; Nsrc = 512; K = 2048;
    }
    float mx = 0.f;
    for (int k = ly; k < K; k += 8)
        mx = fmaxf(mx, fabsf(W[(size_t)k * Nsrc + srccol + lx]));
    smax[ly][lx] = mx;
    __syncthreads();
    if (ly == 0) {
        for (int i = 1; i < 8; i++) mx = fmaxf(mx, smax[i][lx]);
        const float d = mx > 0.f ? mx * (1.f / 32639.f) : 1.f;
        smax[0][lx] = 1.f / d;
        Sd[destrow + lx] = d;
    }
    __syncthreads();
    const float inv = smax[0][lx];
    for (int kb = 0; kb < K; kb += 32) {
        for (int j = ly; j < 32; j += 8) {
            const int q = (int)rintf(W[(size_t)(kb + j) * Nsrc + srccol + lx] * inv);
            const int h = (q + 128) >> 8, l = q - (h << 8);
            tile[j][lx] = (uint32_t)(uint8_t)h | ((uint32_t)(uint8_t)l << 8);
        }
        __syncthreads();
        for (int j = ly; j < 32; j += 8) {
            const uint32_t t = tile[lx][j];
            const size_t o = (size_t)(destrow + j) * K + kb + lx;
            Qh[o] = (int8_t)(t & 255);
            Ql[o] = (int8_t)((t >> 8) & 255);
        }
        __syncthreads();
    }
}

// ---------------------------------------------------------------------------
// quant_rows: f32 [M][KQ] -> s8 limb planes + per-row scale (1 warp / row)
// ---------------------------------------------------------------------------
template <int KQ>
__global__ __launch_bounds__(256)
void quant_rows(const float* __restrict__ src, int8_t* __restrict__ qh,
                int8_t* __restrict__ ql, float* __restrict__ sc) {
    const int w = threadIdx.x >> 5, lane = threadIdx.x & 31;
    const int row = blockIdx.x * 8 + w;
    const float* s = src + (size_t)row * KQ;
    constexpr int J = KQ / 128;
    float4 v[J];
    float mx = 0.f;
#pragma unroll
    for (int j = 0; j < J; j++) {
        v[j] = *(const float4*)(s + j * 128 + lane * 4);
        mx = fmaxf(mx, fmaxf(fmaxf(fabsf(v[j].x), fabsf(v[j].y)),
                             fmaxf(fabsf(v[j].z), fabsf(v[j].w))));
    }
#pragma unroll
    for (int o = 16; o; o >>= 1) mx = fmaxf(mx, __shfl_xor_sync(0xffffffffu, mx, o));
    const float d = mx > 0.f ? mx * (1.f / 32639.f) : 1.f;
    const float inv = 1.f / d;
    if (lane == 0) sc[row] = d;
#pragma unroll
    for (int j = 0; j < J; j++) {
        const int q0 = (int)rintf(v[j].x * inv), q1 = (int)rintf(v[j].y * inv);
        const int q2 = (int)rintf(v[j].z * inv), q3 = (int)rintf(v[j].w * inv);
        const int h0 = (q0 + 128) >> 8, h1 = (q1 + 128) >> 8;
        const int h2 = (q2 + 128) >> 8, h3 = (q3 + 128) >> 8;
        const int l0 = q0 - (h0 << 8), l1 = q1 - (h1 << 8);
        const int l2 = q2 - (h2 << 8), l3 = q3 - (h3 << 8);
        *(uint32_t*)(qh + (size_t)row * KQ + j * 128 + lane * 4) =
            (h0 & 255) | ((h1 & 255) << 8) | ((h2 & 255) << 16) | ((h3 & 255) << 24);
        *(uint32_t*)(ql + (size_t)row * KQ + j * 128 + lane * 4) =
            (l0 & 255) | ((l1 & 255) << 8) | ((l2 & 255) << 16) | ((l3 & 255) << 24);
    }
}

// ---------------------------------------------------------------------------
// int8 2-limb GEMM: v = (A@B^T)*sa*sb + bias. Tile 128x128, BK=128, 3-stage,
// 8 warps 2x4 (warp 64x32). EPI: 0 relu->f32; 1 +res->f32; 2 -> bf16 planes.
// ---------------------------------------------------------------------------
constexpr int I8_STGB = 65536;
constexpr int SMEM_I8 = 3 * I8_STGB;

template <int EPI>
__global__ __launch_bounds__(256, 1)
void gemm_i8(const int8_t* __restrict__ Ah_, const int8_t* __restrict__ Al_,
             const int8_t* __restrict__ Bh_, const int8_t* __restrict__ Bl_,
             const float* __restrict__ sa, const float* __restrict__ sb,
             const float* __restrict__ bias, const float* __restrict__ res,
             float* __restrict__ out,
             uint16_t* __restrict__ Ch, uint16_t* __restrict__ Cl,
             int Nout, int K) {
    extern __shared__ char smraw[];
    const uint32_t sbase = cvta_s(smraw);
    const int tid = threadIdx.x, wid = tid >> 5, lane = tid & 31;
    const int wm = wid >> 2, wn = wid & 3;
    const int mB = blockIdx.y * 128, nB = blockIdx.x * 128;
    const int l7 = lane & 7, l8 = (lane >> 3) & 1, l16 = lane >> 4;

    const int trow = tid >> 3, tch = tid & 7;
    const uint32_t dst0 = trow * 128 + (((uint32_t)tch ^ (trow & 7)) << 4);
    const int8_t* bp[4];
    bp[0] = Ah_ + (size_t)(mB + trow) * K + tch * 16;
    bp[1] = Al_ + (size_t)(mB + trow) * K + tch * 16;
    bp[2] = Bh_ + (size_t)(nB + trow) * K + tch * 16;
    bp[3] = Bl_ + (size_t)(nB + trow) * K + tch * 16;

    int hh[4][4][4], cr[4][4][4];
#pragma unroll
    for (int a = 0; a < 4; a++)
#pragma unroll
        for (int b = 0; b < 4; b++)
#pragma unroll
            for (int c = 0; c < 4; c++) { hh[a][b][c] = 0; cr[a][b][c] = 0; }

    auto issue = [&](int s) {
        const uint32_t stb = sbase + (s % 3) * I8_STGB;
        const int kg = s * 128;
#pragma unroll
        for (int pl = 0; pl < 4; pl++) {
            const int8_t* gp = bp[pl] + kg;
#pragma unroll
            for (int i2 = 0; i2 < 4; i2++)
                CP16(stb + pl * 16384 + dst0 + i2 * 4096, gp + (size_t)i2 * 32 * K);
        }
        CPCOMMIT();
    };

    const int nT = K >> 7;
    issue(0);
    if (nT > 1) issue(1);

    const uint32_t raBase[4] = {
        (uint32_t)(wm * 64 + 0 + l8 * 8 + l7),  (uint32_t)(wm * 64 + 16 + l8 * 8 + l7),
        (uint32_t)(wm * 64 + 32 + l8 * 8 + l7), (uint32_t)(wm * 64 + 48 + l8 * 8 + l7)};
    const uint32_t rbBase[2] = {
        (uint32_t)(wn * 32 + l8 * 8 + l7), (uint32_t)(wn * 32 + 16 + l8 * 8 + l7)};

    for (int t = 0; t < nT; t++) {
        cpwait(t < nT - 1 ? 1 : 0);
        __syncthreads();
        if (t + 2 < nT) issue(t + 2);
        const uint32_t stb = sbase + (t % 3) * I8_STGB;
#pragma unroll
        for (int b = 0; b < 4; b++) {
            uint32_t ahf[4][4], alf[4][4];
#pragma unroll
            for (int mi = 0; mi < 4; mi++) {
                const uint32_t r = raBase[mi];
                const uint32_t base = stb + r * 128;
                const uint32_t ch = (uint32_t)((2 * b + l16) ^ (r & 7)) << 4;
                LDSM4(ahf[mi][0], ahf[mi][1], ahf[mi][2], ahf[mi][3], base + ch);
                LDSM4(alf[mi][0], alf[mi][1], alf[mi][2], alf[mi][3], base + 16384 + ch);
            }
#pragma unroll
            for (int j2 = 0; j2 < 2; j2++) {
                const uint32_t r = rbBase[j2];
                const uint32_t baseB = stb + 32768 + r * 128;
                const uint32_t ch = (uint32_t)((2 * b + l16) ^ (r & 7)) << 4;
                uint32_t bh0, bh1, bh2, bh3, bl0, bl1, bl2, bl3;
                LDSM4(bh0, bh1, bh2, bh3, baseB + ch);
                LDSM4(bl0, bl1, bl2, bl3, baseB + 16384 + ch);
#pragma unroll
                for (int mi = 0; mi < 4; mi++) {
                    imma32(hh[mi][2 * j2],     ahf[mi], bh0, bh2);
                    imma32(hh[mi][2 * j2 + 1], ahf[mi], bh1, bh3);
                }
#pragma unroll
                for (int mi = 0; mi < 4; mi++) {
                    imma32(cr[mi][2 * j2],     ahf[mi], bl0, bl2);
                    imma32(cr[mi][2 * j2 + 1], ahf[mi], bl1, bl3);
                }
#pragma unroll
                for (int mi = 0; mi < 4; mi++) {
                    imma32(cr[mi][2 * j2],     alf[mi], bh0, bh2);
                    imma32(cr[mi][2 * j2 + 1], alf[mi], bh1, bh3);
                }
            }
        }
    }

#pragma unroll
    for (int mi = 0; mi < 4; mi++) {
        const int r0 = mB + wm * 64 + mi * 16 + (lane >> 2);
        const int r1 = r0 + 8;
        const float sa0 = sa[r0], sa1 = sa[r1];
#pragma unroll
        for (int nj = 0; nj < 4; nj++) {
            const int c = nB + wn * 32 + nj * 8 + 2 * (lane & 3);
            const float sb0 = sb[c], sb1 = sb[c + 1];
            const float b0 = bias[c], b1v = bias[c + 1];
            float v0 = ((float)hh[mi][nj][0] * 65536.f + (float)cr[mi][nj][0] * 256.f) * (sa0 * sb0) + b0;
            float v1 = ((float)hh[mi][nj][1] * 65536.f + (float)cr[mi][nj][1] * 256.f) * (sa0 * sb1) + b1v;
            float v2 = ((float)hh[mi][nj][2] * 65536.f + (float)cr[mi][nj][2] * 256.f) * (sa1 * sb0) + b0;
            float v3 = ((float)hh[mi][nj][3] * 65536.f + (float)cr[mi][nj][3] * 256.f) * (sa1 * sb1) + b1v;
            if (EPI == 0) {
                v0 = fmaxf(v0, 0.f); v1 = fmaxf(v1, 0.f);
                v2 = fmaxf(v2, 0.f); v3 = fmaxf(v3, 0.f);
            }
            if (EPI == 1) {
                const float2 rv0 = *(const float2*)(res + (size_t)r0 * Nout + c);
                const float2 rv1 = *(const float2*)(res + (size_t)r1 * Nout + c);
                v0 += rv0.x; v1 += rv0.y; v2 += rv1.x; v3 += rv1.y;
            }
            if (EPI == 2) {
                uint16_t h0, l0, h1, l1;
                split2(v0, h0, l0); split2(v1, h1, l1);
                *(uint32_t*)(Ch + (size_t)r0 * Nout + c) = (uint32_t)h0 | ((uint32_t)h1 << 16);
                *(uint32_t*)(Cl + (size_t)r0 * Nout + c) = (uint32_t)l0 | ((uint32_t)l1 << 16);
                split2(v2, h0, l0); split2(v3, h1, l1);
                *(uint32_t*)(Ch + (size_t)r1 * Nout + c) = (uint32_t)h0 | ((uint32_t)h1 << 16);
                *(uint32_t*)(Cl + (size_t)r1 * Nout + c) = (uint32_t)l0 | ((uint32_t)l1 << 16);
            } else {
                *(float2*)(out + (size_t)r0 * Nout + c) = make_float2(v0, v1);
                *(float2*)(out + (size_t)r1 * Nout + c) = make_float2(v2, v3);
            }
        }
    }
}

// ---------------------------------------------------------------------------
// Attention on bf16 planes (as R8) — output now f32.
// ---------------------------------------------------------------------------
constexpr int SMEM_ATTN = 6 * 32768;

__global__ __launch_bounds__(256, 1)
void attn_kernel(const uint16_t* __restrict__ qh, const uint16_t* __restrict__ ql,
                 float* __restrict__ Of) {
    extern __shared__ char smraw[];
    const uint32_t sb = cvta_s(smraw);
    const uint32_t QH = sb, QL = sb + 32768, KH = sb + 65536, KL = sb + 98304;
    const uint32_t VH = sb + 131072, VL = sb + 163840;

    const int tid = threadIdx.x, bh = blockIdx.x;
    const int bb = bh >> 2, head = bh & 3;
    const size_t rowbase = (size_t)bb * Ss * NQKV;
    const int coloff = head * 128;
    const size_t obase = (size_t)bb * Ss * Ee + (size_t)coloff;

#pragma unroll
    for (int i = 0; i < 48; i++) {
        const int idx = tid + i * 256;
        const int p = idx >> 11, rem = idx & 2047;
        const int row = rem >> 4, c = rem & 15;
        const uint16_t* base = (p & 1) ? ql : qh;
        const size_t src = rowbase + (size_t)row * NQKV + (p >> 1) * 512 + coloff + c * 8;
        CP16(sb + p * 32768 + row * 256 + ((uint32_t)(c ^ (row & 7)) << 4), base + src);
    }
    CPCOMMIT();
    cpwait(0);
    __syncthreads();

    const int wid = tid >> 5, lane = tid & 31;
    const int g = lane >> 2, q = lane & 3;
    const int l7 = lane & 7, l8 = (lane >> 3) & 1, l16 = lane >> 4;
    const int rbase = wid * 16;
    const int ra = rbase + l8 * 8 + l7;

    float acc[16][4];
#pragma unroll
    for (int j = 0; j < 16; j++)
#pragma unroll
        for (int c = 0; c < 4; c++) acc[j][c] = 0.f;

#pragma unroll
    for (int kk = 0; kk < 8; kk++) {
        const uint32_t ca = ((uint32_t)((2 * kk + l16) ^ (ra & 7)) << 4) + ra * 256;
        uint32_t ah[4], al[4];
        LDSM4(ah[0], ah[1], ah[2], ah[3], QH + ca);
        LDSM4(al[0], al[1], al[2], al[3], QL + ca);
#pragma unroll
        for (int j2 = 0; j2 < 8; j2++) {
            const int rb = j2 * 16 + l8 * 8 + l7;
            const uint32_t cb = ((uint32_t)((2 * kk + l16) ^ (rb & 7)) << 4) + rb * 256;
            uint32_t bh_[4], bl_[4];
            LDSM4(bh_[0], bh_[1], bh_[2], bh_[3], KH + cb);
            LDSM4(bl_[0], bl_[1], bl_[2], bl_[3], KL + cb);
            mma3(acc[j2 * 2],     ah, al, bh_[0], bh_[2], bl_[0], bl_[2]);
            mma3(acc[j2 * 2 + 1], ah, al, bh_[1], bh_[3], bl_[1], bl_[3]);
        }
    }

    float m0 = -1e30f, m1 = -1e30f;
#pragma unroll
    for (int j = 0; j < 16; j++) {
        m0 = fmaxf(m0, fmaxf(acc[j][0], acc[j][1]));
        m1 = fmaxf(m1, fmaxf(acc[j][2], acc[j][3]));
    }
    m0 = fmaxf(m0, __shfl_xor_sync(0xffffffffu, m0, 1));
    m0 = fmaxf(m0, __shfl_xor_sync(0xffffffffu, m0, 2));
    m1 = fmaxf(m1, __shfl_xor_sync(0xffffffffu, m1, 1));
    m1 = fmaxf(m1, __shfl_xor_sync(0xffffffffu, m1, 2));
    float s0 = 0.f, s1 = 0.f;
#pragma unroll
    for (int j = 0; j < 16; j++) {
        acc[j][0] = expf(acc[j][0] - m0);
        acc[j][1] = expf(acc[j][1] - m0);
        acc[j][2] = expf(acc[j][2] - m1);
        acc[j][3] = expf(acc[j][3] - m1);
        s0 += acc[j][0] + acc[j][1];
        s1 += acc[j][2] + acc[j][3];
    }
    s0 += __shfl_xor_sync(0xffffffffu, s0, 1);
    s0 += __shfl_xor_sync(0xffffffffu, s0, 2);
    s1 += __shfl_xor_sync(0xffffffffu, s1, 1);
    s1 += __shfl_xor_sync(0xffffffffu, s1, 2);
    const float r0s = 1.f / s0, r1s = 1.f / s1;

    const int pr0 = rbase + g, pr1 = pr0 + 8;
#pragma unroll
    for (int j = 0; j < 16; j++) {
        const uint32_t off0 = pr0 * 256 + ((uint32_t)(j ^ (pr0 & 7)) << 4) + 4 * q;
        const uint32_t off1 = pr1 * 256 + ((uint32_t)(j ^ (pr1 & 7)) << 4) + 4 * q;
        uint16_t h0, l0, h1, l1;
        split2(acc[j][0] * r0s, h0, l0); split2(acc[j][1] * r0s, h1, l1);
        STS32(QH + off0, (uint32_t)h0 | ((uint32_t)h1 << 16));
        STS32(QL + off0, (uint32_t)l0 | ((uint32_t)l1 << 16));
        split2(acc[j][2] * r1s, h0, l0); split2(acc[j][3] * r1s, h1, l1);
        STS32(QH + off1, (uint32_t)h0 | ((uint32_t)h1 << 16));
        STS32(QL + off1, (uint32_t)l0 | ((uint32_t)l1 << 16));
    }
    __syncwarp();

    float acc2[16][4];
#pragma unroll
    for (int j = 0; j < 16; j++)
#pragma unroll
        for (int c = 0; c < 4; c++) acc2[j][c] = 0.f;

#pragma unroll
    for (int kk = 0; kk < 8; kk++) {
        const uint32_t ca = ((uint32_t)((2 * kk + l16) ^ (ra & 7)) << 4) + ra * 256;
        uint32_t ah[4], al[4];
        LDSM4(ah[0], ah[1], ah[2], ah[3], QH + ca);
        LDSM4(al[0], al[1], al[2], al[3], QL + ca);
        const int krow = kk * 16 + l8 * 8 + l7;
#pragma unroll
        for (int j2 = 0; j2 < 8; j2++) {
            const int cj = j2 * 2 + l16;
            const uint32_t cb = ((uint32_t)(cj ^ (krow & 7)) << 4) + krow * 256;
            uint32_t vh_[4], vl_[4];
            LDSM4T(vh_[0], vh_[1], vh_[2], vh_[3], VH + cb);
            LDSM4T(vl_[0], vl_[1], vl_[2], vl_[3], VL + cb);
            mma3(acc2[j2 * 2],     ah, al, vh_[0], vh_[1], vl_[0], vl_[1]);
            mma3(acc2[j2 * 2 + 1], ah, al, vh_[2], vh_[3], vl_[2], vl_[3]);
        }
    }

#pragma unroll
    for (int j = 0; j < 16; j++) {
        const int c = j * 8 + 2 * q;
        const size_t o0 = obase + (size_t)(rbase + g) * Ee + c;
        const size_t o1 = o0 + (size_t)8 * Ee;
        *(float2*)(Of + o0) = make_float2(acc2[j][0], acc2[j][1]);
        *(float2*)(Of + o1) = make_float2(acc2[j][2], acc2[j][3]);
    }
}

// ---------------------------------------------------------------------------
// launch
// ---------------------------------------------------------------------------
extern "C" void kernel_launch(void* const* d_in, const int* in_sizes, int n_in,
                              void* d_out, int out_size) {
    (void)in_sizes; (void)n_in; (void)out_size;
    const float* x  = (const float*)d_in[0];
    const float* wq = (const float*)d_in[1];
    const float* bq = (const float*)d_in[2];
    const float* wk = (const float*)d_in[3];
    const float* bk = (const float*)d_in[4];
    const float* wv = (const float*)d_in[5];
    const float* bv = (const float*)d_in[6];
    const float* wo = (const float*)d_in[7];
    const float* bo = (const float*)d_in[8];
    const float* w1 = (const float*)d_in[9];
    const float* b1 = (const float*)d_in[10];
    const float* w2 = (const float*)d_in[11];
    const float* b2 = (const float*)d_in[12];
    float* out = (float*)d_out;

    int8_t *xqh, *xql, *atqh, *atql, *x1qh, *x1ql, *hqh, *hql;
    int8_t *wqkvqh, *wqkvql, *woqh, *woql, *w1qh, *w1ql, *w2qh, *w2ql;
    uint16_t *qh, *ql;
    float *sx, *sat, *sx1, *sh, *swqkv, *swo, *sw1, *sw2;
    float *attf, *x1f, *hf, *bqkv;
    cudaGetSymbolAddress((void**)&xqh, g_xqh);     cudaGetSymbolAddress((void**)&xql, g_xql);
    cudaGetSymbolAddress((void**)&sx, g_sx);
    cudaGetSymbolAddress((void**)&qh, g_qh);       cudaGetSymbolAddress((void**)&ql, g_ql);
    cudaGetSymbolAddress((void**)&attf, g_attf);
    cudaGetSymbolAddress((void**)&atqh, g_atqh);   cudaGetSymbolAddress((void**)&atql, g_atql);
    cudaGetSymbolAddress((void**)&sat, g_sat);
    cudaGetSymbolAddress((void**)&x1f, g_x1f);
    cudaGetSymbolAddress((void**)&x1qh, g_x1qh);   cudaGetSymbolAddress((void**)&x1ql, g_x1ql);
    cudaGetSymbolAddress((void**)&sx1, g_sx1);
    cudaGetSymbolAddress((void**)&hf, g_hf);
    cudaGetSymbolAddress((void**)&hqh, g_hqh);     cudaGetSymbolAddress((void**)&hql, g_hql);
    cudaGetSymbolAddress((void**)&sh, g_sh);
    cudaGetSymbolAddress((void**)&wqkvqh, g_wqkvqh); cudaGetSymbolAddress((void**)&wqkvql, g_wqkvql);
    cudaGetSymbolAddress((void**)&swqkv, g_swqkv);
    cudaGetSymbolAddress((void**)&woqh, g_woqh);   cudaGetSymbolAddress((void**)&woql, g_woql);
    cudaGetSymbolAddress((void**)&swo, g_swo);
    cudaGetSymbolAddress((void**)&w1qh, g_w1qh);   cudaGetSymbolAddress((void**)&w1ql, g_w1ql);
    cudaGetSymbolAddress((void**)&sw1, g_sw1);
    cudaGetSymbolAddress((void**)&w2qh, g_w2qh);   cudaGetSymbolAddress((void**)&w2ql, g_w2ql);
    cudaGetSymbolAddress((void**)&sw2, g_sw2);
    cudaGetSymbolAddress((void**)&bqkv, g_bqkv);

    cudaFuncSetAttribute(gemm_i8<0>, cudaFuncAttributeMaxDynamicSharedMemorySize, SMEM_I8);
    cudaFuncSetAttribute(gemm_i8<1>, cudaFuncAttributeMaxDynamicSharedMemorySize, SMEM_I8);
    cudaFuncSetAttribute(gemm_i8<2>, cudaFuncAttributeMaxDynamicSharedMemorySize, SMEM_I8);
    cudaFuncSetAttribute(attn_kernel, cudaFuncAttributeMaxDynamicSharedMemorySize, SMEM_ATTN);

    // 0: prep (bias concat + int8 quant of all weights)
    prep_all<<<150, 256>>>(bq, bk, bv, wq, wk, wv, wo, w1, w2);
    // 1: quantize x rows
    quant_rows<Ee><<<MM / 8, 256>>>(x, xqh, xql, sx);
    // 2: fused QKV (int8) -> bf16 planes
    gemm_i8<2><<<dim3(12, 384), 256, SMEM_I8>>>(xqh, xql, wqkvqh, wqkvql, sx, swqkv,
                                                bqkv, nullptr, nullptr, qh, ql, NQKV, Ee);
    // 3: attention -> f32
    attn_kernel<<<Bb * 4, 256, SMEM_ATTN>>>(qh, ql, attf);
    // 4: quantize attention rows
    quant_rows<Ee><<<MM / 8, 256>>>(attf, atqh, atql, sat);
    // 5: x1 = x + attn @ wo + bo (int8)  <- ncu slot
    gemm_i8<1><<<dim3(4, 384), 256, SMEM_I8>>>(atqh, atql, woqh, woql, sat, swo,
                                               bo, x, x1f, nullptr, nullptr, Ee, Ee);
    // 6: quantize x1 rows
    quant_rows<Ee><<<MM / 8, 256>>>(x1f, x1qh, x1ql, sx1);
    // 7: h = relu(x1 @ w1 + b1) (int8)
    gemm_i8<0><<<dim3(16, 384), 256, SMEM_I8>>>(x1qh, x1ql, w1qh, w1ql, sx1, sw1,
                                                b1, nullptr, hf, nullptr, nullptr, Ff, Ee);
    // 8: quantize h rows
    quant_rows<Ff><<<MM / 8, 256>>>(hf, hqh, hql, sh);
    // 9: out = x1 + h @ w2 + b2 (int8)
    gemm_i8<1><<<dim3(4, 384), 256, SMEM_I8>>>(hqh, hql, w2qh, w2ql, sh, sw2,
                                               b2, x1f, out, nullptr, nullptr, Ee, Ff);
}